// round 13
// baseline (speedup 1.0000x reference)
#include <cuda_runtime.h>
#include <cuda_bf16.h>
#include <mma.h>
#include <math.h>
#include <cstdint>

using namespace nvcuda;

#define BSZ 4
#define SEQ 512
#define DM 1024
#define NH 16
#define NKV 4
#define HD 64
#define NROWS (BSZ*SEQ)          // 2048
#define OUT_ELEMS (BSZ*SEQ*DM)
#define NQK 1280                 // combined q|k output cols

typedef __nv_bfloat16 bf16;

// Scratch (device globals; no runtime allocation allowed)
__device__ float g_xq[NROWS * DM];                  // 8 MB (post-rope)
__device__ float g_xkT[BSZ * NKV * HD * SEQ];       // 2 MB (post-rope, transposed)
__device__ bf16 g_xh[NROWS * DM],  g_xl[NROWS * DM];
__device__ bf16 g_wqkh[DM * NQK], g_wqkl[DM * NQK];  // combined wq|wk
__device__ bf16 g_wvh[DM * NKV*HD], g_wvl[DM * NKV*HD];
__device__ bf16 g_woh[DM * DM],    g_wol[DM * DM];
__device__ bf16 g_ah[(size_t)64 * SEQ * SEQ], g_al[(size_t)64 * SEQ * SEQ];
__device__ bf16 g_wsh[(size_t)64 * SEQ * DM], g_wsl[(size_t)64 * SEQ * DM];
__device__ bf16 g_oph[NROWS * DM], g_opl[NROWS * DM];

// ===========================================================================
// helpers
// ===========================================================================
__device__ __forceinline__ void split_write4(bf16* __restrict__ H, bf16* __restrict__ L,
                                             size_t off, float4 v) {
    bf16 h0 = __float2bfloat16(v.x);
    bf16 h1 = __float2bfloat16(v.y);
    bf16 h2 = __float2bfloat16(v.z);
    bf16 h3 = __float2bfloat16(v.w);
    __nv_bfloat162 hh0; hh0.x = h0; hh0.y = h1;
    __nv_bfloat162 hh1; hh1.x = h2; hh1.y = h3;
    *(__nv_bfloat162*)(H + off)     = hh0;
    *(__nv_bfloat162*)(H + off + 2) = hh1;
    __nv_bfloat162 ll0, ll1;
    ll0.x = __float2bfloat16(v.x - __bfloat162float(h0));
    ll0.y = __float2bfloat16(v.y - __bfloat162float(h1));
    ll1.x = __float2bfloat16(v.z - __bfloat162float(h2));
    ll1.y = __float2bfloat16(v.w - __bfloat162float(h3));
    *(__nv_bfloat162*)(L + off)     = ll0;
    *(__nv_bfloat162*)(L + off + 2) = ll1;
}

__device__ __forceinline__ void cp_async16(uint32_t saddr, const void* gptr) {
    asm volatile("cp.async.cg.shared.global [%0], [%1], 16;" :: "r"(saddr), "l"(gptr));
}
__device__ __forceinline__ void cp_commit() { asm volatile("cp.async.commit_group;"); }
__device__ __forceinline__ void cp_wait0()  { asm volatile("cp.async.wait_group 0;"); }
__device__ __forceinline__ void cp_wait1()  { asm volatile("cp.async.wait_group 1;"); }

// ======================= merged operand prep ===============================
__global__ void prep_all(const float* __restrict__ x, const float* __restrict__ wq,
                         const float* __restrict__ wk, const float* __restrict__ wv,
                         const float* __restrict__ wo,
                         bf16* xh, bf16* xl, bf16* wqkh, bf16* wqkl,
                         bf16* wvh, bf16* wvl, bf16* woh, bf16* wol) {
    int idx = blockIdx.x * blockDim.x + threadIdx.x;
    if (idx < 524288) {                       // x: 2048x1024
        float4 v = ((const float4*)x)[idx];
        split_write4(xh, xl, (size_t)idx * 4, v);
    } else if (idx < 786432) {                // wq -> wqk cols 0..1023
        int o = idx - 524288;
        int r = o >> 8, c4 = o & 255;
        float4 v = ((const float4*)wq)[o];
        split_write4(wqkh, wqkl, (size_t)r * NQK + c4 * 4, v);
    } else if (idx < 851968) {                // wk -> wqk cols 1024..1279
        int o = idx - 786432;
        int r = o >> 6, c4 = o & 63;
        float4 v = ((const float4*)wk)[o];
        split_write4(wqkh, wqkl, (size_t)r * NQK + 1024 + c4 * 4, v);
    } else if (idx < 917504) {                // wv
        int o = idx - 851968;
        float4 v = ((const float4*)wv)[o];
        split_write4(wvh, wvl, (size_t)o * 4, v);
    } else if (idx < 1179648) {               // wo
        int o = idx - 917504;
        float4 v = ((const float4*)wo)[o];
        split_write4(woh, wol, (size_t)o * 4, v);
    }
}

// ===========================================================================
// WMMA GEMM core. 3-term bf16 split (AhBh + AhBl + AlBh), fp32 acc.
// 8 warps, warp tile 32 x WNW; CTA tile BM x BN; BK=32, 3-stage cp.async
// pipeline (2 chunks in flight) for pre-split operands.
// PA/PB: operand pre-split (h,l) bf16 -> cp.async straight to smem.
//        otherwise f32, register-staged with in-loop conversion.
// EPI: 0 = fp32 out; 1 = bf16 (h,l) out; 3 = RoPE + q/kT-split out (projqk).
// ===========================================================================
template<int BM, int BN, int WNW, bool PA, bool PB, int EPI>
__device__ __forceinline__ void gcore(
        const bf16* __restrict__ Ah_g, const bf16* __restrict__ Al_g,
        const float* __restrict__ Af_g, size_t lda,
        const bf16* __restrict__ Bh_g, const bf16* __restrict__ Bl_g,
        const float* __restrict__ Bf_g, size_t ldb,
        float* __restrict__ Cf, bf16* __restrict__ Ch, bf16* __restrict__ Cl,
        size_t ldc, float* __restrict__ Tp,
        const float* __restrict__ fcos, const float* __restrict__ fsin,
        int crow0, int ccol0, int kceil) {
    constexpr int APAD = 40;
    constexpr int BPAD = BN + 8;
    constexpr int ASZ  = BM * APAD;
    constexpr int BSZ_ = 32 * BPAD;
    constexpr int BUFSZ = 2 * ASZ + 2 * BSZ_;
    constexpr int N8A = BM / 64 > 0 ? BM / 64 : 1;
    constexpr int N4A = BM / 32;
    constexpr int N8B = BN / 64;
    constexpr int N4B = BN / 32;
    constexpr int WR = BM / 32;
    constexpr int NI = WNW / 16;
    static_assert(WR * (BN / WNW) == 8, "need 8 warps");

    extern __shared__ char smraw[];
    bf16* smbase = (bf16*)smraw;
    uint32_t smu = (uint32_t)__cvta_generic_to_shared(smbase);

    int tid = threadIdx.x;
    int w = tid >> 5;
    int wm = w % WR;
    int wn = w / WR;

    wmma::fragment<wmma::accumulator, 16, 16, 16, float> acc[2][NI];
#pragma unroll
    for (int mi = 0; mi < 2; mi++)
#pragma unroll
        for (int ni = 0; ni < NI; ni++) wmma::fill_fragment(acc[mi][ni], 0.0f);

    float4 raf[PA ? 1 : N4A];
    float4 rbf[PB ? 1 : N4B];

    auto issueA = [&](int k0, int bufsel) {
#pragma unroll
        for (int it = 0; it < N8A; it++) {
            int idx8 = tid + it * 256;
            int row = idx8 >> 2, kc = (idx8 & 3) * 8;
            uint32_t so = smu + (uint32_t)(bufsel * BUFSZ + row * APAD + kc) * 2;
            cp_async16(so, Ah_g + (size_t)row * lda + k0 + kc);
            cp_async16(so + ASZ * 2, Al_g + (size_t)row * lda + k0 + kc);
        }
    };
    auto issueB = [&](int k0, int bufsel) {
#pragma unroll
        for (int it = 0; it < N8B; it++) {
            int idx8 = tid + it * 256;
            int row = idx8 / (BN / 8), nc = (idx8 % (BN / 8)) * 8;
            uint32_t so = smu + (uint32_t)(bufsel * BUFSZ + 2 * ASZ + row * BPAD + nc) * 2;
            cp_async16(so, Bh_g + (size_t)(k0 + row) * ldb + nc);
            cp_async16(so + BSZ_ * 2, Bl_g + (size_t)(k0 + row) * ldb + nc);
        }
    };

    int nch = kceil >> 5;
    int cur = 0;

    // prologue: 2 chunks in flight
    if constexpr (PA || PB) {
        if constexpr (PA) issueA(0, 0);
        if constexpr (PB) issueB(0, 0);
        cp_commit();
        if (nch > 1) {
            if constexpr (PA) issueA(32, 1);
            if constexpr (PB) issueB(32, 1);
            cp_commit();
        }
    }
    if constexpr (!PA) {
#pragma unroll
        for (int it = 0; it < N4A; it++) {
            int idx4 = tid + it * 256;
            int row = idx4 >> 3, kc = (idx4 & 7) * 4;
            raf[it] = *(const float4*)&Af_g[(size_t)row * lda + kc];
        }
    }
    if constexpr (!PB) {
#pragma unroll
        for (int it = 0; it < N4B; it++) {
            int idx4 = tid + it * 256;
            int row = idx4 / (BN / 4), nc = (idx4 % (BN / 4)) * 4;
            rbf[it] = *(const float4*)&Bf_g[(size_t)row * ldb + nc];
        }
    }

    for (int ch = 0; ch < nch; ch++) {
        bf16* Ah = smbase + cur * BUFSZ;
        bf16* Al = Ah + ASZ;
        bf16* Bh = Al + ASZ;
        bf16* Bl = Bh + BSZ_;

        // f32-staged operands: convert + store for this chunk (disjoint region
        // from in-flight cp.async of the same buffer)
        if constexpr (!PA) {
#pragma unroll
            for (int it = 0; it < N4A; it++) {
                int idx4 = tid + it * 256;
                int row = idx4 >> 3, kc = (idx4 & 7) * 4;
                split_write4(Ah, Al, row * APAD + kc, raf[it]);
            }
        }
        if constexpr (!PB) {
#pragma unroll
            for (int it = 0; it < N4B; it++) {
                int idx4 = tid + it * 256;
                int row = idx4 / (BN / 4), nc = (idx4 % (BN / 4)) * 4;
                split_write4(Bh, Bl, row * BPAD + nc, rbf[it]);
            }
        }
        if constexpr (PA || PB) {
            if (ch + 1 < nch) cp_wait1(); else cp_wait0();
        }
        __syncthreads();

        // issue chunk ch+2 into the buffer freed by chunk ch-1's MMA
        if constexpr (PA || PB) {
            if (ch + 2 < nch) {
                int k0 = (ch + 2) * 32;
                int nb = cur + 2 >= 3 ? cur - 1 : cur + 2;
                if constexpr (PA) issueA(k0, nb);
                if constexpr (PB) issueB(k0, nb);
                cp_commit();
            }
        }
        // f32 register prefetch for chunk ch+1 (overlaps MMA)
        if (ch + 1 < nch) {
            int k0 = (ch + 1) * 32;
            if constexpr (!PA) {
#pragma unroll
                for (int it = 0; it < N4A; it++) {
                    int idx4 = tid + it * 256;
                    int row = idx4 >> 3, kc = (idx4 & 7) * 4;
                    raf[it] = *(const float4*)&Af_g[(size_t)row * lda + k0 + kc];
                }
            }
            if constexpr (!PB) {
#pragma unroll
                for (int it = 0; it < N4B; it++) {
                    int idx4 = tid + it * 256;
                    int row = idx4 / (BN / 4), nc = (idx4 % (BN / 4)) * 4;
                    rbf[it] = *(const float4*)&Bf_g[(size_t)(k0 + row) * ldb + nc];
                }
            }
        }

#pragma unroll
        for (int kk = 0; kk < 32; kk += 16) {
            wmma::fragment<wmma::matrix_a, 16, 16, 16, bf16, wmma::row_major> ah[2], al[2];
#pragma unroll
            for (int mi = 0; mi < 2; mi++) {
                int r0 = (wm * 32 + mi * 16) * APAD + kk;
                wmma::load_matrix_sync(ah[mi], Ah + r0, APAD);
                wmma::load_matrix_sync(al[mi], Al + r0, APAD);
            }
#pragma unroll
            for (int ni = 0; ni < NI; ni++) {
                wmma::fragment<wmma::matrix_b, 16, 16, 16, bf16, wmma::row_major> bh, bl;
                int c0 = kk * BPAD + wn * WNW + ni * 16;
                wmma::load_matrix_sync(bh, Bh + c0, BPAD);
                wmma::load_matrix_sync(bl, Bl + c0, BPAD);
#pragma unroll
                for (int mi = 0; mi < 2; mi++) {
                    wmma::mma_sync(acc[mi][ni], ah[mi], bh, acc[mi][ni]);
                    wmma::mma_sync(acc[mi][ni], ah[mi], bl, acc[mi][ni]);
                    wmma::mma_sync(acc[mi][ni], al[mi], bh, acc[mi][ni]);
                }
            }
        }
        cur = cur + 1 >= 3 ? 0 : cur + 1;
    }

    // ---- epilogue via fp32 smem staging
    __syncthreads();
    float* stg = (float*)smraw;
#pragma unroll
    for (int mi = 0; mi < 2; mi++)
#pragma unroll
        for (int ni = 0; ni < NI; ni++)
            wmma::store_matrix_sync(stg + (size_t)(wm * 32 + mi * 16) * BN + wn * WNW + ni * 16,
                                    acc[mi][ni], BN, wmma::mem_row_major);
    __syncthreads();
    constexpr int NE4 = BM * BN / 1024;
#pragma unroll
    for (int it = 0; it < NE4; it++) {
        int idx4 = tid + it * 256;
        int row = idx4 / (BN / 4), c = (idx4 % (BN / 4)) * 4;
        float4 v = *(const float4*)&stg[row * BN + c];
        if constexpr (EPI == 3) {
            int grow = crow0 + row;
            int gcol = ccol0 + c;
            int pos = grow & (SEQ - 1);
            int p = (gcol & 63) >> 1;
            float c0v = fcos[pos * 32 + p],     s0v = fsin[pos * 32 + p];
            float c1v = fcos[pos * 32 + p + 1], s1v = fsin[pos * 32 + p + 1];
            float4 o;
            o.x = v.x * c0v - v.y * s0v;
            o.y = v.x * s0v + v.y * c0v;
            o.z = v.z * c1v - v.w * s1v;
            o.w = v.z * s1v + v.w * c1v;
            if (gcol < DM) {
                *(float4*)&Cf[(size_t)grow * DM + gcol] = o;   // xq
            } else {
                int kvd = gcol - DM;                            // kv*64 + d
                int b = grow >> 9, j = grow & 511;
                float* base = Tp + ((size_t)(b * NKV * HD + kvd)) * SEQ + j;
                base[0]       = o.x;
                base[SEQ]     = o.y;
                base[2 * SEQ] = o.z;
                base[3 * SEQ] = o.w;
            }
        } else if constexpr (EPI == 1) {
            split_write4(Ch, Cl, (size_t)row * ldc + c, v);
        } else {
            *(float4*)&Cf[(size_t)row * ldc + c] = v;
        }
    }
}

// smem byte sizes (3 pipeline stages)
#define SM_BIG3  ((2*(128*40) + 2*(32*136)) * 2 * 3)   // 113664 (1 CTA/SM)
#define SM_WS33  ((2*(64*40)  + 2*(32*136)) * 2 * 3)   // 82944  (2 CTA/SM)
#define SM_WSV3  ((2*(64*40)  + 2*(32*72))  * 2 * 3)   // 58368  (2 CTA/SM)

// ======================= GEMM wrappers =====================================
// Combined Q|K projection, fused RoPE + K-transpose epilogue. grid (10, 16).
__global__ __launch_bounds__(256) void gemm_projqk(const bf16* __restrict__ Ah,
                                                   const bf16* __restrict__ Al,
                                                   const bf16* __restrict__ Bh,
                                                   const bf16* __restrict__ Bl,
                                                   float* __restrict__ xq,
                                                   float* __restrict__ xkT,
                                                   const float* __restrict__ fcos,
                                                   const float* __restrict__ fsin) {
    size_t ao = (size_t)blockIdx.y * 128 * DM;
    size_t bo = (size_t)blockIdx.x * 128;
    gcore<128, 128, 64, true, true, 3>(Ah + ao, Al + ao, nullptr, DM,
                                       Bh + bo, Bl + bo, nullptr, NQK,
                                       xq, nullptr, nullptr, DM, xkT,
                                       fcos, fsin, blockIdx.y * 128, blockIdx.x * 128, DM);
}

__global__ __launch_bounds__(256) void gemm_wo(const bf16* __restrict__ Ah,
                                               const bf16* __restrict__ Al,
                                               const bf16* __restrict__ Bh,
                                               const bf16* __restrict__ Bl,
                                               float* __restrict__ C) {
    size_t ao = (size_t)blockIdx.y * 128 * DM;
    size_t bo = (size_t)blockIdx.x * 128;
    float* Cb = C + (size_t)blockIdx.y * 128 * DM + (size_t)blockIdx.x * 128;
    gcore<128, 128, 64, true, true, 0>(Ah + ao, Al + ao, nullptr, DM,
                                       Bh + bo, Bl + bo, nullptr, DM,
                                       Cb, nullptr, nullptr, DM, nullptr,
                                       nullptr, nullptr, 0, 0, DM);
}

// ws: 64x128 tile, 2 CTAs/SM, 3-stage pipeline; heavy (large i) blocks first.
__global__ __launch_bounds__(256, 2) void gemm_ws(const bf16* __restrict__ ah,
                                                  const bf16* __restrict__ al,
                                                  const float* __restrict__ symbols,
                                                  bf16* __restrict__ wsh,
                                                  bf16* __restrict__ wsl) {
    int i = SEQ - 1 - blockIdx.y;            // heavy K first
    int c0 = blockIdx.x * 128;
    int kceil = (i + 32) & ~31;              // attn[j>i]==0 exactly
    size_t ao = (size_t)i * SEQ;
    const float* B = symbols + (size_t)i * SEQ * DM + c0;
    size_t co = (size_t)i * DM + c0;
    gcore<64, 128, 32, true, false, 1>(ah + ao, al + ao, nullptr, (size_t)SEQ * SEQ,
                                       nullptr, nullptr, B, DM,
                                       nullptr, wsh + co, wsl + co, (size_t)SEQ * DM, nullptr,
                                       nullptr, nullptr, 0, 0, kceil);
}

// wsv: 64x64 tile, 2 CTAs/SM, 3-stage pipeline.
__global__ __launch_bounds__(256, 2) void gemm_wsv(const bf16* __restrict__ wsh,
                                                   const bf16* __restrict__ wsl,
                                                   const bf16* __restrict__ wvh,
                                                   const bf16* __restrict__ wvl,
                                                   bf16* __restrict__ oph,
                                                   bf16* __restrict__ opl) {
    int i0 = blockIdx.x * 64;
    int row = blockIdx.y;
    int b = row >> 4, h = row & 15, kv = h >> 2;
    size_t ao = ((size_t)row * SEQ + i0) * DM;
    size_t bo = (size_t)kv * HD;
    size_t co = ((size_t)b * SEQ + i0) * DM + h * HD;
    gcore<64, 64, 16, true, true, 1>(wsh + ao, wsl + ao, nullptr, DM,
                                     wvh + bo, wvl + bo, nullptr, NKV * HD,
                                     nullptr, oph + co, opl + co, DM, nullptr,
                                     nullptr, nullptr, 0, 0, DM);
}

// ======================= Scores + softmax (causal-skipped) =================
template<int NQ4>
__device__ __forceinline__ void scores_body(const float qra[HD], const float qrb[HD],
                                            const float* __restrict__ kT,
                                            int ia, int ib, int lane,
                                            float* __restrict__ attn,
                                            bf16* __restrict__ ah_g,
                                            bf16* __restrict__ al_g,
                                            size_t basea, size_t baseb) {
    float sa[NQ4 * 4], sb[NQ4 * 4];
#pragma unroll
    for (int t = 0; t < NQ4 * 4; t++) { sa[t] = 0.f; sb[t] = 0.f; }

#pragma unroll 4
    for (int d = 0; d < HD; d++) {
        float qa = qra[d];
        float qb = qrb[d];
        const float* kd = kT + (size_t)d * SEQ + lane * 4;
#pragma unroll
        for (int q4 = 0; q4 < NQ4; q4++) {
            float4 kv4 = *(const float4*)&kd[q4 * 128];
            sa[q4 * 4 + 0] += qa * kv4.x;  sb[q4 * 4 + 0] += qb * kv4.x;
            sa[q4 * 4 + 1] += qa * kv4.y;  sb[q4 * 4 + 1] += qb * kv4.y;
            sa[q4 * 4 + 2] += qa * kv4.z;  sb[q4 * 4 + 2] += qb * kv4.z;
            sa[q4 * 4 + 3] += qa * kv4.w;  sb[q4 * 4 + 3] += qb * kv4.w;
        }
    }

    float ma = -INFINITY, mb = -INFINITY;
#pragma unroll
    for (int q4 = 0; q4 < NQ4; q4++)
#pragma unroll
        for (int e = 0; e < 4; e++) {
            int j = q4 * 128 + lane * 4 + e;
            int t = q4 * 4 + e;
            sa[t] = (j <= ia) ? sa[t] * 0.125f : -INFINITY;
            sb[t] = (j <= ib) ? sb[t] * 0.125f : -INFINITY;
            ma = fmaxf(ma, sa[t]);
            mb = fmaxf(mb, sb[t]);
        }
#pragma unroll
    for (int o = 16; o > 0; o >>= 1) {
        ma = fmaxf(ma, __shfl_xor_sync(0xFFFFFFFF, ma, o));
        mb = fmaxf(mb, __shfl_xor_sync(0xFFFFFFFF, mb, o));
    }
    float suma = 0.f, sumb = 0.f;
#pragma unroll
    for (int t = 0; t < NQ4 * 4; t++) {
        sa[t] = (sa[t] == -INFINITY) ? 0.f : __expf(sa[t] - ma);
        sb[t] = (sb[t] == -INFINITY) ? 0.f : __expf(sb[t] - mb);
        suma += sa[t];
        sumb += sb[t];
    }
#pragma unroll
    for (int o = 16; o > 0; o >>= 1) {
        suma += __shfl_xor_sync(0xFFFFFFFF, suma, o);
        sumb += __shfl_xor_sync(0xFFFFFFFF, sumb, o);
    }
    float inva = 1.0f / suma;
    float invb = 1.0f / sumb;

#pragma unroll
    for (int q4 = 0; q4 < NQ4; q4++) {
        int j = q4 * 128 + lane * 4;
        float4 va = make_float4(sa[q4 * 4] * inva, sa[q4 * 4 + 1] * inva,
                                sa[q4 * 4 + 2] * inva, sa[q4 * 4 + 3] * inva);
        float4 vb = make_float4(sb[q4 * 4] * invb, sb[q4 * 4 + 1] * invb,
                                sb[q4 * 4 + 2] * invb, sb[q4 * 4 + 3] * invb);
        *(float4*)&attn[basea + j] = va;
        *(float4*)&attn[baseb + j] = vb;
        split_write4(ah_g, al_g, basea + j, va);
        split_write4(ah_g, al_g, baseb + j, vb);
    }
    float4 z = make_float4(0.f, 0.f, 0.f, 0.f);
#pragma unroll
    for (int q4 = NQ4; q4 < 4; q4++) {
        int j = q4 * 128 + lane * 4;
        *(float4*)&attn[basea + j] = z;
        *(float4*)&attn[baseb + j] = z;
    }
}

__global__ __launch_bounds__(256) void scores2(const float* __restrict__ xq,
                                               const float* __restrict__ xkT,
                                               float* __restrict__ attn,
                                               bf16* __restrict__ ah_g,
                                               bf16* __restrict__ al_g) {
    int i0 = blockIdx.x * 16;
    int h = blockIdx.y, b = blockIdx.z;
    int kv = h >> 2;
    int tid = threadIdx.x;
    int w = tid >> 5, lane = tid & 31;

    __shared__ float qs[16][HD];
    {
        int idx = tid * 4;
        int row = idx >> 6, d = idx & 63;
        *(float4*)&qs[row][d] =
            *(const float4*)&xq[((size_t)(b * SEQ + i0 + row)) * DM + h * HD + d];
    }
    __syncthreads();

    int ia = i0 + w * 2;
    int ib = ia + 1;
    const float* kT = xkT + ((size_t)(b * NKV + kv)) * HD * SEQ;
    size_t basea = ((size_t)((b * NH + h) * SEQ + ia)) * SEQ;
    size_t baseb = basea + SEQ;
    int nq4 = min(4, (i0 + 16 + 127) >> 7);

    switch (nq4) {
        case 1: scores_body<1>(qs[w*2], qs[w*2+1], kT, ia, ib, lane, attn, ah_g, al_g, basea, baseb); break;
        case 2: scores_body<2>(qs[w*2], qs[w*2+1], kT, ia, ib, lane, attn, ah_g, al_g, basea, baseb); break;
        case 3: scores_body<3>(qs[w*2], qs[w*2+1], kT, ia, ib, lane, attn, ah_g, al_g, basea, baseb); break;
        default: scores_body<4>(qs[w*2], qs[w*2+1], kT, ia, ib, lane, attn, ah_g, al_g, basea, baseb); break;
    }
}

// ===========================================================================
extern "C" void kernel_launch(void* const* d_in, const int* in_sizes, int n_in,
                              void* d_out, int out_size) {
    const float* x       = (const float*)d_in[0];
    const float* symbols = (const float*)d_in[1];
    const float* fcos    = (const float*)d_in[2];
    const float* fsin    = (const float*)d_in[3];
    const float* wq      = (const float*)d_in[4];
    const float* wk      = (const float*)d_in[5];
    const float* wv      = (const float*)d_in[6];
    const float* wo      = (const float*)d_in[7];

    float* out  = (float*)d_out;
    float* attn = out + OUT_ELEMS;

    float *p_xq, *p_xkT;
    bf16 *p_xh, *p_xl, *p_wqkh, *p_wqkl, *p_wvh, *p_wvl, *p_woh, *p_wol;
    bf16 *p_ah, *p_al, *p_wsh, *p_wsl, *p_oph, *p_opl;
    cudaGetSymbolAddress((void**)&p_xq, g_xq);
    cudaGetSymbolAddress((void**)&p_xkT, g_xkT);
    cudaGetSymbolAddress((void**)&p_xh, g_xh);     cudaGetSymbolAddress((void**)&p_xl, g_xl);
    cudaGetSymbolAddress((void**)&p_wqkh, g_wqkh); cudaGetSymbolAddress((void**)&p_wqkl, g_wqkl);
    cudaGetSymbolAddress((void**)&p_wvh, g_wvh);   cudaGetSymbolAddress((void**)&p_wvl, g_wvl);
    cudaGetSymbolAddress((void**)&p_woh, g_woh);   cudaGetSymbolAddress((void**)&p_wol, g_wol);
    cudaGetSymbolAddress((void**)&p_ah, g_ah);     cudaGetSymbolAddress((void**)&p_al, g_al);
    cudaGetSymbolAddress((void**)&p_wsh, g_wsh);   cudaGetSymbolAddress((void**)&p_wsl, g_wsl);
    cudaGetSymbolAddress((void**)&p_oph, g_oph);   cudaGetSymbolAddress((void**)&p_opl, g_opl);

    cudaFuncSetAttribute(gemm_projqk, cudaFuncAttributeMaxDynamicSharedMemorySize, SM_BIG3);
    cudaFuncSetAttribute(gemm_wo,     cudaFuncAttributeMaxDynamicSharedMemorySize, SM_BIG3);
    cudaFuncSetAttribute(gemm_ws,     cudaFuncAttributeMaxDynamicSharedMemorySize, SM_WS33);
    cudaFuncSetAttribute(gemm_wsv,    cudaFuncAttributeMaxDynamicSharedMemorySize, SM_WSV3);

    prep_all<<<4608, 256>>>(x, wq, wk, wv, wo, p_xh, p_xl, p_wqkh, p_wqkl,
                            p_wvh, p_wvl, p_woh, p_wol);                               // 0
    gemm_projqk<<<dim3(NQK / 128, NROWS / 128), 256, SM_BIG3>>>(p_xh, p_xl,
                                                                p_wqkh, p_wqkl,
                                                                p_xq, p_xkT,
                                                                fcos, fsin);           // 1
    scores2<<<dim3(SEQ / 16, NH, BSZ), 256>>>(p_xq, p_xkT, attn, p_ah, p_al);          // 2
    gemm_ws<<<dim3(DM / 128, SEQ), 256, SM_WS33>>>(p_ah, p_al, symbols, p_wsh, p_wsl); // 3  <- ncu
    gemm_wsv<<<dim3(SEQ / 64, 64), 256, SM_WSV3>>>(p_wsh, p_wsl, p_wvh, p_wvl,
                                                   p_oph, p_opl);                      // 4
    gemm_wo<<<dim3(DM / 128, NROWS / 128), 256, SM_BIG3>>>(p_oph, p_opl, p_woh, p_wol, out); // 5
}

// round 14
// speedup vs baseline: 1.0442x; 1.0442x over previous
#include <cuda_runtime.h>
#include <cuda_bf16.h>
#include <mma.h>
#include <math.h>
#include <cstdint>

using namespace nvcuda;

#define BSZ 4
#define SEQ 512
#define DM 1024
#define NH 16
#define NKV 4
#define HD 64
#define NROWS (BSZ*SEQ)          // 2048
#define OUT_ELEMS (BSZ*SEQ*DM)
#define NQK 1280                 // combined q|k output cols

typedef __nv_bfloat16 bf16;

// Scratch (device globals; no runtime allocation allowed)
__device__ float g_xq[NROWS * DM];                  // 8 MB (post-rope)
__device__ float g_xkT[BSZ * NKV * HD * SEQ];       // 2 MB (post-rope, transposed)
__device__ bf16 g_xh[NROWS * DM],  g_xl[NROWS * DM];
__device__ bf16 g_wqkh[DM * NQK], g_wqkl[DM * NQK];  // combined wq|wk
__device__ bf16 g_wvh[DM * NKV*HD], g_wvl[DM * NKV*HD];
__device__ bf16 g_woh[DM * DM],    g_wol[DM * DM];
__device__ bf16 g_ah[(size_t)64 * SEQ * SEQ], g_al[(size_t)64 * SEQ * SEQ];
__device__ bf16 g_wsh[(size_t)64 * SEQ * DM], g_wsl[(size_t)64 * SEQ * DM];
__device__ bf16 g_oph[NROWS * DM], g_opl[NROWS * DM];

// ===========================================================================
// helpers
// ===========================================================================
__device__ __forceinline__ void split_write4(bf16* __restrict__ H, bf16* __restrict__ L,
                                             size_t off, float4 v) {
    bf16 h0 = __float2bfloat16(v.x);
    bf16 h1 = __float2bfloat16(v.y);
    bf16 h2 = __float2bfloat16(v.z);
    bf16 h3 = __float2bfloat16(v.w);
    __nv_bfloat162 hh0; hh0.x = h0; hh0.y = h1;
    __nv_bfloat162 hh1; hh1.x = h2; hh1.y = h3;
    *(__nv_bfloat162*)(H + off)     = hh0;
    *(__nv_bfloat162*)(H + off + 2) = hh1;
    __nv_bfloat162 ll0, ll1;
    ll0.x = __float2bfloat16(v.x - __bfloat162float(h0));
    ll0.y = __float2bfloat16(v.y - __bfloat162float(h1));
    ll1.x = __float2bfloat16(v.z - __bfloat162float(h2));
    ll1.y = __float2bfloat16(v.w - __bfloat162float(h3));
    *(__nv_bfloat162*)(L + off)     = ll0;
    *(__nv_bfloat162*)(L + off + 2) = ll1;
}

__device__ __forceinline__ void cp_async16(uint32_t saddr, const void* gptr) {
    asm volatile("cp.async.cg.shared.global [%0], [%1], 16;" :: "r"(saddr), "l"(gptr));
}
__device__ __forceinline__ void cp_commit() { asm volatile("cp.async.commit_group;"); }
__device__ __forceinline__ void cp_wait0()  { asm volatile("cp.async.wait_group 0;"); }

// ======================= merged operand prep ===============================
__global__ void prep_all(const float* __restrict__ x, const float* __restrict__ wq,
                         const float* __restrict__ wk, const float* __restrict__ wv,
                         const float* __restrict__ wo,
                         bf16* xh, bf16* xl, bf16* wqkh, bf16* wqkl,
                         bf16* wvh, bf16* wvl, bf16* woh, bf16* wol) {
    int idx = blockIdx.x * blockDim.x + threadIdx.x;
    if (idx < 524288) {                       // x: 2048x1024
        float4 v = ((const float4*)x)[idx];
        split_write4(xh, xl, (size_t)idx * 4, v);
    } else if (idx < 786432) {                // wq -> wqk cols 0..1023
        int o = idx - 524288;
        int r = o >> 8, c4 = o & 255;
        float4 v = ((const float4*)wq)[o];
        split_write4(wqkh, wqkl, (size_t)r * NQK + c4 * 4, v);
    } else if (idx < 851968) {                // wk -> wqk cols 1024..1279
        int o = idx - 786432;
        int r = o >> 6, c4 = o & 63;
        float4 v = ((const float4*)wk)[o];
        split_write4(wqkh, wqkl, (size_t)r * NQK + 1024 + c4 * 4, v);
    } else if (idx < 917504) {                // wv
        int o = idx - 851968;
        float4 v = ((const float4*)wv)[o];
        split_write4(wvh, wvl, (size_t)o * 4, v);
    } else if (idx < 1179648) {               // wo
        int o = idx - 917504;
        float4 v = ((const float4*)wo)[o];
        split_write4(woh, wol, (size_t)o * 4, v);
    }
}

// ===========================================================================
// WMMA GEMM core. 3-term bf16 split (AhBh + AhBl + AlBh), fp32 acc.
// 8 warps, warp tile 32 x WNW; CTA tile BM x BN; BK=32 double-buffered cp.async.
// PA/PB: operand pre-split (h,l) bf16 -> cp.async straight to smem.
//        otherwise f32, register-staged with in-loop conversion.
// EPI: 0 = fp32 out; 1 = bf16 (h,l) out; 3 = RoPE + q/kT-split out (projqk).
// ===========================================================================
template<int BM, int BN, int WNW, bool PA, bool PB, int EPI>
__device__ __forceinline__ void gcore(
        const bf16* __restrict__ Ah_g, const bf16* __restrict__ Al_g,
        const float* __restrict__ Af_g, size_t lda,
        const bf16* __restrict__ Bh_g, const bf16* __restrict__ Bl_g,
        const float* __restrict__ Bf_g, size_t ldb,
        float* __restrict__ Cf, bf16* __restrict__ Ch, bf16* __restrict__ Cl,
        size_t ldc, float* __restrict__ Tp,
        const float* __restrict__ fcos, const float* __restrict__ fsin,
        int crow0, int ccol0, int kceil) {
    constexpr int APAD = 40;
    constexpr int BPAD = BN + 8;
    constexpr int ASZ  = BM * APAD;
    constexpr int BSZ_ = 32 * BPAD;
    constexpr int BUFSZ = 2 * ASZ + 2 * BSZ_;
    constexpr int N8A = BM / 64 > 0 ? BM / 64 : 1;
    constexpr int N4A = BM / 32;
    constexpr int N8B = BN / 64;
    constexpr int N4B = BN / 32;
    constexpr int WR = BM / 32;
    constexpr int NI = WNW / 16;
    static_assert(WR * (BN / WNW) == 8, "need 8 warps");

    extern __shared__ char smraw[];
    bf16* smbase = (bf16*)smraw;
    uint32_t smu = (uint32_t)__cvta_generic_to_shared(smbase);

    int tid = threadIdx.x;
    int w = tid >> 5;
    int wm = w % WR;
    int wn = w / WR;

    wmma::fragment<wmma::accumulator, 16, 16, 16, float> acc[2][NI];
#pragma unroll
    for (int mi = 0; mi < 2; mi++)
#pragma unroll
        for (int ni = 0; ni < NI; ni++) wmma::fill_fragment(acc[mi][ni], 0.0f);

    float4 raf[PA ? 1 : N4A];
    float4 rbf[PB ? 1 : N4B];

    auto issueA = [&](int k0, int bufsel) {
#pragma unroll
        for (int it = 0; it < N8A; it++) {
            int idx8 = tid + it * 256;
            int row = idx8 >> 2, kc = (idx8 & 3) * 8;
            uint32_t so = smu + (uint32_t)(bufsel * BUFSZ + row * APAD + kc) * 2;
            cp_async16(so, Ah_g + (size_t)row * lda + k0 + kc);
            cp_async16(so + ASZ * 2, Al_g + (size_t)row * lda + k0 + kc);
        }
    };
    auto issueB = [&](int k0, int bufsel) {
#pragma unroll
        for (int it = 0; it < N8B; it++) {
            int idx8 = tid + it * 256;
            int row = idx8 / (BN / 8), nc = (idx8 % (BN / 8)) * 8;
            uint32_t so = smu + (uint32_t)(bufsel * BUFSZ + 2 * ASZ + row * BPAD + nc) * 2;
            cp_async16(so, Bh_g + (size_t)(k0 + row) * ldb + nc);
            cp_async16(so + BSZ_ * 2, Bl_g + (size_t)(k0 + row) * ldb + nc);
        }
    };

    int nch = kceil >> 5;
    int cur = 0;

    if constexpr (PA) issueA(0, 0);
    if constexpr (PB) issueB(0, 0);
    if constexpr (PA || PB) cp_commit();
    if constexpr (!PA) {
#pragma unroll
        for (int it = 0; it < N4A; it++) {
            int idx4 = tid + it * 256;
            int row = idx4 >> 3, kc = (idx4 & 7) * 4;
            raf[it] = *(const float4*)&Af_g[(size_t)row * lda + kc];
        }
    }
    if constexpr (!PB) {
#pragma unroll
        for (int it = 0; it < N4B; it++) {
            int idx4 = tid + it * 256;
            int row = idx4 / (BN / 4), nc = (idx4 % (BN / 4)) * 4;
            rbf[it] = *(const float4*)&Bf_g[(size_t)row * ldb + nc];
        }
    }

    for (int ch = 0; ch < nch; ch++) {
        bf16* Ah = smbase + cur * BUFSZ;
        bf16* Al = Ah + ASZ;
        bf16* Bh = Al + ASZ;
        bf16* Bl = Bh + BSZ_;

        if constexpr (!PA) {
#pragma unroll
            for (int it = 0; it < N4A; it++) {
                int idx4 = tid + it * 256;
                int row = idx4 >> 3, kc = (idx4 & 7) * 4;
                split_write4(Ah, Al, row * APAD + kc, raf[it]);
            }
        }
        if constexpr (!PB) {
#pragma unroll
            for (int it = 0; it < N4B; it++) {
                int idx4 = tid + it * 256;
                int row = idx4 / (BN / 4), nc = (idx4 % (BN / 4)) * 4;
                split_write4(Bh, Bl, row * BPAD + nc, rbf[it]);
            }
        }
        if constexpr (PA || PB) cp_wait0();
        __syncthreads();

        if (ch + 1 < nch) {
            int k0 = (ch + 1) * 32;
            if constexpr (PA) issueA(k0, cur ^ 1);
            if constexpr (PB) issueB(k0, cur ^ 1);
            if constexpr (PA || PB) cp_commit();
            if constexpr (!PA) {
#pragma unroll
                for (int it = 0; it < N4A; it++) {
                    int idx4 = tid + it * 256;
                    int row = idx4 >> 3, kc = (idx4 & 7) * 4;
                    raf[it] = *(const float4*)&Af_g[(size_t)row * lda + k0 + kc];
                }
            }
            if constexpr (!PB) {
#pragma unroll
                for (int it = 0; it < N4B; it++) {
                    int idx4 = tid + it * 256;
                    int row = idx4 / (BN / 4), nc = (idx4 % (BN / 4)) * 4;
                    rbf[it] = *(const float4*)&Bf_g[(size_t)(k0 + row) * ldb + nc];
                }
            }
        }

#pragma unroll
        for (int kk = 0; kk < 32; kk += 16) {
            wmma::fragment<wmma::matrix_a, 16, 16, 16, bf16, wmma::row_major> ah[2], al[2];
#pragma unroll
            for (int mi = 0; mi < 2; mi++) {
                int r0 = (wm * 32 + mi * 16) * APAD + kk;
                wmma::load_matrix_sync(ah[mi], Ah + r0, APAD);
                wmma::load_matrix_sync(al[mi], Al + r0, APAD);
            }
#pragma unroll
            for (int ni = 0; ni < NI; ni++) {
                wmma::fragment<wmma::matrix_b, 16, 16, 16, bf16, wmma::row_major> bh, bl;
                int c0 = kk * BPAD + wn * WNW + ni * 16;
                wmma::load_matrix_sync(bh, Bh + c0, BPAD);
                wmma::load_matrix_sync(bl, Bl + c0, BPAD);
#pragma unroll
                for (int mi = 0; mi < 2; mi++) {
                    wmma::mma_sync(acc[mi][ni], ah[mi], bh, acc[mi][ni]);
                    wmma::mma_sync(acc[mi][ni], ah[mi], bl, acc[mi][ni]);
                    wmma::mma_sync(acc[mi][ni], al[mi], bh, acc[mi][ni]);
                }
            }
        }
        cur ^= 1;
    }

    // ---- epilogue via fp32 smem staging
    __syncthreads();
    float* stg = (float*)smraw;
#pragma unroll
    for (int mi = 0; mi < 2; mi++)
#pragma unroll
        for (int ni = 0; ni < NI; ni++)
            wmma::store_matrix_sync(stg + (size_t)(wm * 32 + mi * 16) * BN + wn * WNW + ni * 16,
                                    acc[mi][ni], BN, wmma::mem_row_major);
    __syncthreads();
    constexpr int NE4 = BM * BN / 1024;
#pragma unroll
    for (int it = 0; it < NE4; it++) {
        int idx4 = tid + it * 256;
        int row = idx4 / (BN / 4), c = (idx4 % (BN / 4)) * 4;
        float4 v = *(const float4*)&stg[row * BN + c];
        if constexpr (EPI == 3) {
            int grow = crow0 + row;
            int gcol = ccol0 + c;
            int pos = grow & (SEQ - 1);
            int p = (gcol & 63) >> 1;
            float c0v = fcos[pos * 32 + p],     s0v = fsin[pos * 32 + p];
            float c1v = fcos[pos * 32 + p + 1], s1v = fsin[pos * 32 + p + 1];
            float4 o;
            o.x = v.x * c0v - v.y * s0v;
            o.y = v.x * s0v + v.y * c0v;
            o.z = v.z * c1v - v.w * s1v;
            o.w = v.z * s1v + v.w * c1v;
            if (gcol < DM) {
                *(float4*)&Cf[(size_t)grow * DM + gcol] = o;   // xq
            } else {
                int kvd = gcol - DM;                            // kv*64 + d
                int b = grow >> 9, j = grow & 511;
                float* base = Tp + ((size_t)(b * NKV * HD + kvd)) * SEQ + j;
                base[0]       = o.x;
                base[SEQ]     = o.y;
                base[2 * SEQ] = o.z;
                base[3 * SEQ] = o.w;
            }
        } else if constexpr (EPI == 1) {
            split_write4(Ch, Cl, (size_t)row * ldc + c, v);
        } else {
            *(float4*)&Cf[(size_t)row * ldc + c] = v;
        }
    }
}

// smem byte sizes (2 pipeline stages)
#define SM_T64  ((2*(64*40) + 2*(32*136)) * 2 * 2)   // 55296 (64x128 tiles, 2 CTA/SM)
#define SM_WSV2 ((2*(64*40) + 2*(32*72))  * 2 * 2)   // 38912 (64x64 tiles, 2 CTA/SM)

// ======================= GEMM wrappers =====================================
// Combined Q|K projection, fused RoPE + K-transpose epilogue. 64x128 tiles,
// 2 CTAs/SM. grid (NQK/128=10, NROWS/64=32).
__global__ __launch_bounds__(256, 2) void gemm_projqk(const bf16* __restrict__ Ah,
                                                      const bf16* __restrict__ Al,
                                                      const bf16* __restrict__ Bh,
                                                      const bf16* __restrict__ Bl,
                                                      float* __restrict__ xq,
                                                      float* __restrict__ xkT,
                                                      const float* __restrict__ fcos,
                                                      const float* __restrict__ fsin) {
    size_t ao = (size_t)blockIdx.y * 64 * DM;
    size_t bo = (size_t)blockIdx.x * 128;
    gcore<64, 128, 32, true, true, 3>(Ah + ao, Al + ao, nullptr, DM,
                                      Bh + bo, Bl + bo, nullptr, NQK,
                                      xq, nullptr, nullptr, DM, xkT,
                                      fcos, fsin, blockIdx.y * 64, blockIdx.x * 128, DM);
}

// Output projection: 64x128 tiles, 2 CTAs/SM. grid (8, 32).
__global__ __launch_bounds__(256, 2) void gemm_wo(const bf16* __restrict__ Ah,
                                                  const bf16* __restrict__ Al,
                                                  const bf16* __restrict__ Bh,
                                                  const bf16* __restrict__ Bl,
                                                  float* __restrict__ C) {
    size_t ao = (size_t)blockIdx.y * 64 * DM;
    size_t bo = (size_t)blockIdx.x * 128;
    float* Cb = C + (size_t)blockIdx.y * 64 * DM + (size_t)blockIdx.x * 128;
    gcore<64, 128, 32, true, true, 0>(Ah + ao, Al + ao, nullptr, DM,
                                      Bh + bo, Bl + bo, nullptr, DM,
                                      Cb, nullptr, nullptr, DM, nullptr,
                                      nullptr, nullptr, 0, 0, DM);
}

// ws: 64x128 tile, 2 CTAs/SM; heavy (large i) blocks scheduled first.
__global__ __launch_bounds__(256, 2) void gemm_ws(const bf16* __restrict__ ah,
                                                  const bf16* __restrict__ al,
                                                  const float* __restrict__ symbols,
                                                  bf16* __restrict__ wsh,
                                                  bf16* __restrict__ wsl) {
    int i = SEQ - 1 - blockIdx.y;            // heavy K first
    int c0 = blockIdx.x * 128;
    int kceil = (i + 32) & ~31;              // attn[j>i]==0 exactly
    size_t ao = (size_t)i * SEQ;
    const float* B = symbols + (size_t)i * SEQ * DM + c0;
    size_t co = (size_t)i * DM + c0;
    gcore<64, 128, 32, true, false, 1>(ah + ao, al + ao, nullptr, (size_t)SEQ * SEQ,
                                       nullptr, nullptr, B, DM,
                                       nullptr, wsh + co, wsl + co, (size_t)SEQ * DM, nullptr,
                                       nullptr, nullptr, 0, 0, kceil);
}

// wsv: 64x64 tile, 2 CTAs/SM.
__global__ __launch_bounds__(256, 2) void gemm_wsv(const bf16* __restrict__ wsh,
                                                   const bf16* __restrict__ wsl,
                                                   const bf16* __restrict__ wvh,
                                                   const bf16* __restrict__ wvl,
                                                   bf16* __restrict__ oph,
                                                   bf16* __restrict__ opl) {
    int i0 = blockIdx.x * 64;
    int row = blockIdx.y;
    int b = row >> 4, h = row & 15, kv = h >> 2;
    size_t ao = ((size_t)row * SEQ + i0) * DM;
    size_t bo = (size_t)kv * HD;
    size_t co = ((size_t)b * SEQ + i0) * DM + h * HD;
    gcore<64, 64, 16, true, true, 1>(wsh + ao, wsl + ao, nullptr, DM,
                                     wvh + bo, wvl + bo, nullptr, NKV * HD,
                                     nullptr, oph + co, opl + co, DM, nullptr,
                                     nullptr, nullptr, 0, 0, DM);
}

// ======================= Scores + softmax (causal-skipped) =================
template<int NQ4>
__device__ __forceinline__ void scores_body(const float qra[HD], const float qrb[HD],
                                            const float* __restrict__ kT,
                                            int ia, int ib, int lane,
                                            float* __restrict__ attn,
                                            bf16* __restrict__ ah_g,
                                            bf16* __restrict__ al_g,
                                            size_t basea, size_t baseb) {
    float sa[NQ4 * 4], sb[NQ4 * 4];
#pragma unroll
    for (int t = 0; t < NQ4 * 4; t++) { sa[t] = 0.f; sb[t] = 0.f; }

#pragma unroll 4
    for (int d = 0; d < HD; d++) {
        float qa = qra[d];
        float qb = qrb[d];
        const float* kd = kT + (size_t)d * SEQ + lane * 4;
#pragma unroll
        for (int q4 = 0; q4 < NQ4; q4++) {
            float4 kv4 = *(const float4*)&kd[q4 * 128];
            sa[q4 * 4 + 0] += qa * kv4.x;  sb[q4 * 4 + 0] += qb * kv4.x;
            sa[q4 * 4 + 1] += qa * kv4.y;  sb[q4 * 4 + 1] += qb * kv4.y;
            sa[q4 * 4 + 2] += qa * kv4.z;  sb[q4 * 4 + 2] += qb * kv4.z;
            sa[q4 * 4 + 3] += qa * kv4.w;  sb[q4 * 4 + 3] += qb * kv4.w;
        }
    }

    float ma = -INFINITY, mb = -INFINITY;
#pragma unroll
    for (int q4 = 0; q4 < NQ4; q4++)
#pragma unroll
        for (int e = 0; e < 4; e++) {
            int j = q4 * 128 + lane * 4 + e;
            int t = q4 * 4 + e;
            sa[t] = (j <= ia) ? sa[t] * 0.125f : -INFINITY;
            sb[t] = (j <= ib) ? sb[t] * 0.125f : -INFINITY;
            ma = fmaxf(ma, sa[t]);
            mb = fmaxf(mb, sb[t]);
        }
#pragma unroll
    for (int o = 16; o > 0; o >>= 1) {
        ma = fmaxf(ma, __shfl_xor_sync(0xFFFFFFFF, ma, o));
        mb = fmaxf(mb, __shfl_xor_sync(0xFFFFFFFF, mb, o));
    }
    float suma = 0.f, sumb = 0.f;
#pragma unroll
    for (int t = 0; t < NQ4 * 4; t++) {
        sa[t] = (sa[t] == -INFINITY) ? 0.f : __expf(sa[t] - ma);
        sb[t] = (sb[t] == -INFINITY) ? 0.f : __expf(sb[t] - mb);
        suma += sa[t];
        sumb += sb[t];
    }
#pragma unroll
    for (int o = 16; o > 0; o >>= 1) {
        suma += __shfl_xor_sync(0xFFFFFFFF, suma, o);
        sumb += __shfl_xor_sync(0xFFFFFFFF, sumb, o);
    }
    float inva = 1.0f / suma;
    float invb = 1.0f / sumb;

#pragma unroll
    for (int q4 = 0; q4 < NQ4; q4++) {
        int j = q4 * 128 + lane * 4;
        float4 va = make_float4(sa[q4 * 4] * inva, sa[q4 * 4 + 1] * inva,
                                sa[q4 * 4 + 2] * inva, sa[q4 * 4 + 3] * inva);
        float4 vb = make_float4(sb[q4 * 4] * invb, sb[q4 * 4 + 1] * invb,
                                sb[q4 * 4 + 2] * invb, sb[q4 * 4 + 3] * invb);
        *(float4*)&attn[basea + j] = va;
        *(float4*)&attn[baseb + j] = vb;
        split_write4(ah_g, al_g, basea + j, va);
        split_write4(ah_g, al_g, baseb + j, vb);
    }
    float4 z = make_float4(0.f, 0.f, 0.f, 0.f);
#pragma unroll
    for (int q4 = NQ4; q4 < 4; q4++) {
        int j = q4 * 128 + lane * 4;
        *(float4*)&attn[basea + j] = z;
        *(float4*)&attn[baseb + j] = z;
    }
}

__global__ __launch_bounds__(256) void scores2(const float* __restrict__ xq,
                                               const float* __restrict__ xkT,
                                               float* __restrict__ attn,
                                               bf16* __restrict__ ah_g,
                                               bf16* __restrict__ al_g) {
    int i0 = blockIdx.x * 16;
    int h = blockIdx.y, b = blockIdx.z;
    int kv = h >> 2;
    int tid = threadIdx.x;
    int w = tid >> 5, lane = tid & 31;

    __shared__ float qs[16][HD];
    {
        int idx = tid * 4;
        int row = idx >> 6, d = idx & 63;
        *(float4*)&qs[row][d] =
            *(const float4*)&xq[((size_t)(b * SEQ + i0 + row)) * DM + h * HD + d];
    }
    __syncthreads();

    int ia = i0 + w * 2;
    int ib = ia + 1;
    const float* kT = xkT + ((size_t)(b * NKV + kv)) * HD * SEQ;
    size_t basea = ((size_t)((b * NH + h) * SEQ + ia)) * SEQ;
    size_t baseb = basea + SEQ;
    int nq4 = min(4, (i0 + 16 + 127) >> 7);

    switch (nq4) {
        case 1: scores_body<1>(qs[w*2], qs[w*2+1], kT, ia, ib, lane, attn, ah_g, al_g, basea, baseb); break;
        case 2: scores_body<2>(qs[w*2], qs[w*2+1], kT, ia, ib, lane, attn, ah_g, al_g, basea, baseb); break;
        case 3: scores_body<3>(qs[w*2], qs[w*2+1], kT, ia, ib, lane, attn, ah_g, al_g, basea, baseb); break;
        default: scores_body<4>(qs[w*2], qs[w*2+1], kT, ia, ib, lane, attn, ah_g, al_g, basea, baseb); break;
    }
}

// ===========================================================================
extern "C" void kernel_launch(void* const* d_in, const int* in_sizes, int n_in,
                              void* d_out, int out_size) {
    const float* x       = (const float*)d_in[0];
    const float* symbols = (const float*)d_in[1];
    const float* fcos    = (const float*)d_in[2];
    const float* fsin    = (const float*)d_in[3];
    const float* wq      = (const float*)d_in[4];
    const float* wk      = (const float*)d_in[5];
    const float* wv      = (const float*)d_in[6];
    const float* wo      = (const float*)d_in[7];

    float* out  = (float*)d_out;
    float* attn = out + OUT_ELEMS;

    float *p_xq, *p_xkT;
    bf16 *p_xh, *p_xl, *p_wqkh, *p_wqkl, *p_wvh, *p_wvl, *p_woh, *p_wol;
    bf16 *p_ah, *p_al, *p_wsh, *p_wsl, *p_oph, *p_opl;
    cudaGetSymbolAddress((void**)&p_xq, g_xq);
    cudaGetSymbolAddress((void**)&p_xkT, g_xkT);
    cudaGetSymbolAddress((void**)&p_xh, g_xh);     cudaGetSymbolAddress((void**)&p_xl, g_xl);
    cudaGetSymbolAddress((void**)&p_wqkh, g_wqkh); cudaGetSymbolAddress((void**)&p_wqkl, g_wqkl);
    cudaGetSymbolAddress((void**)&p_wvh, g_wvh);   cudaGetSymbolAddress((void**)&p_wvl, g_wvl);
    cudaGetSymbolAddress((void**)&p_woh, g_woh);   cudaGetSymbolAddress((void**)&p_wol, g_wol);
    cudaGetSymbolAddress((void**)&p_ah, g_ah);     cudaGetSymbolAddress((void**)&p_al, g_al);
    cudaGetSymbolAddress((void**)&p_wsh, g_wsh);   cudaGetSymbolAddress((void**)&p_wsl, g_wsl);
    cudaGetSymbolAddress((void**)&p_oph, g_oph);   cudaGetSymbolAddress((void**)&p_opl, g_opl);

    cudaFuncSetAttribute(gemm_projqk, cudaFuncAttributeMaxDynamicSharedMemorySize, SM_T64);
    cudaFuncSetAttribute(gemm_wo,     cudaFuncAttributeMaxDynamicSharedMemorySize, SM_T64);
    cudaFuncSetAttribute(gemm_ws,     cudaFuncAttributeMaxDynamicSharedMemorySize, SM_T64);
    cudaFuncSetAttribute(gemm_wsv,    cudaFuncAttributeMaxDynamicSharedMemorySize, SM_WSV2);

    prep_all<<<4608, 256>>>(x, wq, wk, wv, wo, p_xh, p_xl, p_wqkh, p_wqkl,
                            p_wvh, p_wvl, p_woh, p_wol);                               // 0
    gemm_projqk<<<dim3(NQK / 128, NROWS / 64), 256, SM_T64>>>(p_xh, p_xl,
                                                              p_wqkh, p_wqkl,
                                                              p_xq, p_xkT,
                                                              fcos, fsin);             // 1
    scores2<<<dim3(SEQ / 16, NH, BSZ), 256>>>(p_xq, p_xkT, attn, p_ah, p_al);          // 2
    gemm_ws<<<dim3(DM / 128, SEQ), 256, SM_T64>>>(p_ah, p_al, symbols, p_wsh, p_wsl);  // 3  <- ncu
    gemm_wsv<<<dim3(SEQ / 64, 64), 256, SM_WSV2>>>(p_wsh, p_wsl, p_wvh, p_wvl,
                                                   p_oph, p_opl);                      // 4
    gemm_wo<<<dim3(DM / 128, NROWS / 64), 256, SM_T64>>>(p_oph, p_opl, p_woh, p_wol, out); // 5
}

// round 15
// speedup vs baseline: 1.0677x; 1.0226x over previous
#include <cuda_runtime.h>
#include <cuda_bf16.h>
#include <mma.h>
#include <math.h>
#include <cstdint>

using namespace nvcuda;

#define BSZ 4
#define SEQ 512
#define DM 1024
#define NH 16
#define NKV 4
#define HD 64
#define NROWS (BSZ*SEQ)          // 2048
#define OUT_ELEMS (BSZ*SEQ*DM)
#define NQK 1280                 // combined q|k output cols

typedef __nv_bfloat16 bf16;

// Scratch (device globals; no runtime allocation allowed)
__device__ float g_xq[NROWS * DM];                  // 8 MB (post-rope)
__device__ float g_xkT[BSZ * NKV * HD * SEQ];       // 2 MB (post-rope, transposed)
__device__ bf16 g_xh[NROWS * DM],  g_xl[NROWS * DM];
__device__ bf16 g_wqkh[DM * NQK], g_wqkl[DM * NQK];  // combined wq|wk
__device__ bf16 g_wvh[DM * NKV*HD], g_wvl[DM * NKV*HD];
__device__ bf16 g_woh[DM * DM],    g_wol[DM * DM];
__device__ bf16 g_ah[(size_t)64 * SEQ * SEQ], g_al[(size_t)64 * SEQ * SEQ];
__device__ bf16 g_wsh[(size_t)64 * SEQ * DM], g_wsl[(size_t)64 * SEQ * DM];
__device__ bf16 g_oph[NROWS * DM], g_opl[NROWS * DM];

// ===========================================================================
// helpers
// ===========================================================================
__device__ __forceinline__ void split_write4(bf16* __restrict__ H, bf16* __restrict__ L,
                                             size_t off, float4 v) {
    bf16 h0 = __float2bfloat16(v.x);
    bf16 h1 = __float2bfloat16(v.y);
    bf16 h2 = __float2bfloat16(v.z);
    bf16 h3 = __float2bfloat16(v.w);
    __nv_bfloat162 hh0; hh0.x = h0; hh0.y = h1;
    __nv_bfloat162 hh1; hh1.x = h2; hh1.y = h3;
    *(__nv_bfloat162*)(H + off)     = hh0;
    *(__nv_bfloat162*)(H + off + 2) = hh1;
    __nv_bfloat162 ll0, ll1;
    ll0.x = __float2bfloat16(v.x - __bfloat162float(h0));
    ll0.y = __float2bfloat16(v.y - __bfloat162float(h1));
    ll1.x = __float2bfloat16(v.z - __bfloat162float(h2));
    ll1.y = __float2bfloat16(v.w - __bfloat162float(h3));
    *(__nv_bfloat162*)(L + off)     = ll0;
    *(__nv_bfloat162*)(L + off + 2) = ll1;
}

__device__ __forceinline__ void cp_async16(uint32_t saddr, const void* gptr) {
    asm volatile("cp.async.cg.shared.global [%0], [%1], 16;" :: "r"(saddr), "l"(gptr));
}
__device__ __forceinline__ void cp_commit() { asm volatile("cp.async.commit_group;"); }
__device__ __forceinline__ void cp_wait0()  { asm volatile("cp.async.wait_group 0;"); }

// ======================= merged operand prep ===============================
__global__ void prep_all(const float* __restrict__ x, const float* __restrict__ wq,
                         const float* __restrict__ wk, const float* __restrict__ wv,
                         const float* __restrict__ wo,
                         bf16* xh, bf16* xl, bf16* wqkh, bf16* wqkl,
                         bf16* wvh, bf16* wvl, bf16* woh, bf16* wol) {
    int idx = blockIdx.x * blockDim.x + threadIdx.x;
    if (idx < 524288) {                       // x: 2048x1024
        float4 v = ((const float4*)x)[idx];
        split_write4(xh, xl, (size_t)idx * 4, v);
    } else if (idx < 786432) {                // wq -> wqk cols 0..1023
        int o = idx - 524288;
        int r = o >> 8, c4 = o & 255;
        float4 v = ((const float4*)wq)[o];
        split_write4(wqkh, wqkl, (size_t)r * NQK + c4 * 4, v);
    } else if (idx < 851968) {                // wk -> wqk cols 1024..1279
        int o = idx - 786432;
        int r = o >> 6, c4 = o & 63;
        float4 v = ((const float4*)wk)[o];
        split_write4(wqkh, wqkl, (size_t)r * NQK + 1024 + c4 * 4, v);
    } else if (idx < 917504) {                // wv
        int o = idx - 851968;
        float4 v = ((const float4*)wv)[o];
        split_write4(wvh, wvl, (size_t)o * 4, v);
    } else if (idx < 1179648) {               // wo
        int o = idx - 917504;
        float4 v = ((const float4*)wo)[o];
        split_write4(woh, wol, (size_t)o * 4, v);
    }
}

// ===========================================================================
// WMMA GEMM core. 3-term bf16 split (AhBh + AhBl + AlBh), fp32 acc.
// NT threads (NT/32 warps), warp tile 32 x WNW; CTA tile BM x BN; BK=32
// double-buffered cp.async.
// PA/PB: operand pre-split (h,l) bf16 -> cp.async straight to smem.
//        otherwise f32, register-staged with in-loop conversion.
// EPI: 0 = fp32 out; 1 = bf16 (h,l) out; 3 = RoPE + q/kT-split out (projqk).
// ===========================================================================
template<int BM, int BN, int WNW, int NT, bool PA, bool PB, int EPI>
__device__ __forceinline__ void gcore(
        const bf16* __restrict__ Ah_g, const bf16* __restrict__ Al_g,
        const float* __restrict__ Af_g, size_t lda,
        const bf16* __restrict__ Bh_g, const bf16* __restrict__ Bl_g,
        const float* __restrict__ Bf_g, size_t ldb,
        float* __restrict__ Cf, bf16* __restrict__ Ch, bf16* __restrict__ Cl,
        size_t ldc, float* __restrict__ Tp,
        const float* __restrict__ fcos, const float* __restrict__ fsin,
        int crow0, int ccol0, int kceil) {
    constexpr int APAD = 40;
    constexpr int BPAD = BN + 8;
    constexpr int ASZ  = BM * APAD;
    constexpr int BSZ_ = 32 * BPAD;
    constexpr int BUFSZ = 2 * ASZ + 2 * BSZ_;
    constexpr int NW  = NT / 32;
    constexpr int N8A = (BM * 4) / NT > 0 ? (BM * 4) / NT : 1;
    constexpr int N4A = (BM * 8) / NT;
    constexpr int N8B = (BN * 4) / NT;
    constexpr int N4B = (BN * 8) / NT;
    constexpr int WR = BM / 32;
    constexpr int NI = WNW / 16;
    static_assert(WR * (BN / WNW) == NW, "warp grid mismatch");

    extern __shared__ char smraw[];
    bf16* smbase = (bf16*)smraw;
    uint32_t smu = (uint32_t)__cvta_generic_to_shared(smbase);

    int tid = threadIdx.x;
    int w = tid >> 5;
    int wm = w % WR;
    int wn = w / WR;

    wmma::fragment<wmma::accumulator, 16, 16, 16, float> acc[2][NI];
#pragma unroll
    for (int mi = 0; mi < 2; mi++)
#pragma unroll
        for (int ni = 0; ni < NI; ni++) wmma::fill_fragment(acc[mi][ni], 0.0f);

    float4 raf[PA ? 1 : N4A];
    float4 rbf[PB ? 1 : N4B];

    auto issueA = [&](int k0, int bufsel) {
#pragma unroll
        for (int it = 0; it < N8A; it++) {
            int idx8 = tid + it * NT;
            int row = idx8 >> 2, kc = (idx8 & 3) * 8;
            uint32_t so = smu + (uint32_t)(bufsel * BUFSZ + row * APAD + kc) * 2;
            cp_async16(so, Ah_g + (size_t)row * lda + k0 + kc);
            cp_async16(so + ASZ * 2, Al_g + (size_t)row * lda + k0 + kc);
        }
    };
    auto issueB = [&](int k0, int bufsel) {
#pragma unroll
        for (int it = 0; it < N8B; it++) {
            int idx8 = tid + it * NT;
            int row = idx8 / (BN / 8), nc = (idx8 % (BN / 8)) * 8;
            uint32_t so = smu + (uint32_t)(bufsel * BUFSZ + 2 * ASZ + row * BPAD + nc) * 2;
            cp_async16(so, Bh_g + (size_t)(k0 + row) * ldb + nc);
            cp_async16(so + BSZ_ * 2, Bl_g + (size_t)(k0 + row) * ldb + nc);
        }
    };

    int nch = kceil >> 5;
    int cur = 0;

    if constexpr (PA) issueA(0, 0);
    if constexpr (PB) issueB(0, 0);
    if constexpr (PA || PB) cp_commit();
    if constexpr (!PA) {
#pragma unroll
        for (int it = 0; it < N4A; it++) {
            int idx4 = tid + it * NT;
            int row = idx4 >> 3, kc = (idx4 & 7) * 4;
            raf[it] = *(const float4*)&Af_g[(size_t)row * lda + kc];
        }
    }
    if constexpr (!PB) {
#pragma unroll
        for (int it = 0; it < N4B; it++) {
            int idx4 = tid + it * NT;
            int row = idx4 / (BN / 4), nc = (idx4 % (BN / 4)) * 4;
            rbf[it] = *(const float4*)&Bf_g[(size_t)row * ldb + nc];
        }
    }

    for (int ch = 0; ch < nch; ch++) {
        bf16* Ah = smbase + cur * BUFSZ;
        bf16* Al = Ah + ASZ;
        bf16* Bh = Al + ASZ;
        bf16* Bl = Bh + BSZ_;

        if constexpr (!PA) {
#pragma unroll
            for (int it = 0; it < N4A; it++) {
                int idx4 = tid + it * NT;
                int row = idx4 >> 3, kc = (idx4 & 7) * 4;
                split_write4(Ah, Al, row * APAD + kc, raf[it]);
            }
        }
        if constexpr (!PB) {
#pragma unroll
            for (int it = 0; it < N4B; it++) {
                int idx4 = tid + it * NT;
                int row = idx4 / (BN / 4), nc = (idx4 % (BN / 4)) * 4;
                split_write4(Bh, Bl, row * BPAD + nc, rbf[it]);
            }
        }
        if constexpr (PA || PB) cp_wait0();
        __syncthreads();

        if (ch + 1 < nch) {
            int k0 = (ch + 1) * 32;
            if constexpr (PA) issueA(k0, cur ^ 1);
            if constexpr (PB) issueB(k0, cur ^ 1);
            if constexpr (PA || PB) cp_commit();
            if constexpr (!PA) {
#pragma unroll
                for (int it = 0; it < N4A; it++) {
                    int idx4 = tid + it * NT;
                    int row = idx4 >> 3, kc = (idx4 & 7) * 4;
                    raf[it] = *(const float4*)&Af_g[(size_t)row * lda + k0 + kc];
                }
            }
            if constexpr (!PB) {
#pragma unroll
                for (int it = 0; it < N4B; it++) {
                    int idx4 = tid + it * NT;
                    int row = idx4 / (BN / 4), nc = (idx4 % (BN / 4)) * 4;
                    rbf[it] = *(const float4*)&Bf_g[(size_t)(k0 + row) * ldb + nc];
                }
            }
        }

#pragma unroll
        for (int kk = 0; kk < 32; kk += 16) {
            wmma::fragment<wmma::matrix_a, 16, 16, 16, bf16, wmma::row_major> ah[2], al[2];
#pragma unroll
            for (int mi = 0; mi < 2; mi++) {
                int r0 = (wm * 32 + mi * 16) * APAD + kk;
                wmma::load_matrix_sync(ah[mi], Ah + r0, APAD);
                wmma::load_matrix_sync(al[mi], Al + r0, APAD);
            }
#pragma unroll
            for (int ni = 0; ni < NI; ni++) {
                wmma::fragment<wmma::matrix_b, 16, 16, 16, bf16, wmma::row_major> bh, bl;
                int c0 = kk * BPAD + wn * WNW + ni * 16;
                wmma::load_matrix_sync(bh, Bh + c0, BPAD);
                wmma::load_matrix_sync(bl, Bl + c0, BPAD);
#pragma unroll
                for (int mi = 0; mi < 2; mi++) {
                    wmma::mma_sync(acc[mi][ni], ah[mi], bh, acc[mi][ni]);
                    wmma::mma_sync(acc[mi][ni], ah[mi], bl, acc[mi][ni]);
                    wmma::mma_sync(acc[mi][ni], al[mi], bh, acc[mi][ni]);
                }
            }
        }
        cur ^= 1;
    }

    // ---- epilogue via fp32 smem staging
    __syncthreads();
    float* stg = (float*)smraw;
#pragma unroll
    for (int mi = 0; mi < 2; mi++)
#pragma unroll
        for (int ni = 0; ni < NI; ni++)
            wmma::store_matrix_sync(stg + (size_t)(wm * 32 + mi * 16) * BN + wn * WNW + ni * 16,
                                    acc[mi][ni], BN, wmma::mem_row_major);
    __syncthreads();
    constexpr int NE4 = BM * BN / (4 * NT);
#pragma unroll
    for (int it = 0; it < NE4; it++) {
        int idx4 = tid + it * NT;
        int row = idx4 / (BN / 4), c = (idx4 % (BN / 4)) * 4;
        float4 v = *(const float4*)&stg[row * BN + c];
        if constexpr (EPI == 3) {
            int grow = crow0 + row;
            int gcol = ccol0 + c;
            int pos = grow & (SEQ - 1);
            int p = (gcol & 63) >> 1;
            float c0v = fcos[pos * 32 + p],     s0v = fsin[pos * 32 + p];
            float c1v = fcos[pos * 32 + p + 1], s1v = fsin[pos * 32 + p + 1];
            float4 o;
            o.x = v.x * c0v - v.y * s0v;
            o.y = v.x * s0v + v.y * c0v;
            o.z = v.z * c1v - v.w * s1v;
            o.w = v.z * s1v + v.w * c1v;
            if (gcol < DM) {
                *(float4*)&Cf[(size_t)grow * DM + gcol] = o;   // xq
            } else {
                int kvd = gcol - DM;                            // kv*64 + d
                int b = grow >> 9, j = grow & 511;
                float* base = Tp + ((size_t)(b * NKV * HD + kvd)) * SEQ + j;
                base[0]       = o.x;
                base[SEQ]     = o.y;
                base[2 * SEQ] = o.z;
                base[3 * SEQ] = o.w;
            }
        } else if constexpr (EPI == 1) {
            split_write4(Ch, Cl, (size_t)row * ldc + c, v);
        } else {
            *(float4*)&Cf[(size_t)row * ldc + c] = v;
        }
    }
}

// smem byte sizes (2 pipeline stages)
#define SM_T64  ((2*(64*40) + 2*(32*136)) * 2 * 2)   // 55296
#define SM_WSV2 ((2*(64*40) + 2*(32*72))  * 2 * 2)   // 38912

// ======================= GEMM wrappers =====================================
// Combined Q|K projection, fused RoPE + K-transpose epilogue. 64x128 tiles,
// 256 thr, 2 CTAs/SM. grid (10, 32).
__global__ __launch_bounds__(256, 2) void gemm_projqk(const bf16* __restrict__ Ah,
                                                      const bf16* __restrict__ Al,
                                                      const bf16* __restrict__ Bh,
                                                      const bf16* __restrict__ Bl,
                                                      float* __restrict__ xq,
                                                      float* __restrict__ xkT,
                                                      const float* __restrict__ fcos,
                                                      const float* __restrict__ fsin) {
    size_t ao = (size_t)blockIdx.y * 64 * DM;
    size_t bo = (size_t)blockIdx.x * 128;
    gcore<64, 128, 32, 256, true, true, 3>(Ah + ao, Al + ao, nullptr, DM,
                                           Bh + bo, Bl + bo, nullptr, NQK,
                                           xq, nullptr, nullptr, DM, xkT,
                                           fcos, fsin, blockIdx.y * 64, blockIdx.x * 128, DM);
}

// Output projection: 64x128 tiles, 256 thr, 2 CTAs/SM. grid (8, 32).
__global__ __launch_bounds__(256, 2) void gemm_wo(const bf16* __restrict__ Ah,
                                                  const bf16* __restrict__ Al,
                                                  const bf16* __restrict__ Bh,
                                                  const bf16* __restrict__ Bl,
                                                  float* __restrict__ C) {
    size_t ao = (size_t)blockIdx.y * 64 * DM;
    size_t bo = (size_t)blockIdx.x * 128;
    float* Cb = C + (size_t)blockIdx.y * 64 * DM + (size_t)blockIdx.x * 128;
    gcore<64, 128, 32, 256, true, true, 0>(Ah + ao, Al + ao, nullptr, DM,
                                           Bh + bo, Bl + bo, nullptr, DM,
                                           Cb, nullptr, nullptr, DM, nullptr,
                                           nullptr, nullptr, 0, 0, DM);
}

// ws: 64x128 tile, 128 threads / 4 warps, warp tile 32x64, 3 CTAs/SM target.
// Heavy (large i) blocks scheduled first.
__global__ __launch_bounds__(128, 3) void gemm_ws(const bf16* __restrict__ ah,
                                                  const bf16* __restrict__ al,
                                                  const float* __restrict__ symbols,
                                                  bf16* __restrict__ wsh,
                                                  bf16* __restrict__ wsl) {
    int i = SEQ - 1 - blockIdx.y;            // heavy K first
    int c0 = blockIdx.x * 128;
    int kceil = (i + 32) & ~31;              // attn[j>i]==0 exactly
    size_t ao = (size_t)i * SEQ;
    const float* B = symbols + (size_t)i * SEQ * DM + c0;
    size_t co = (size_t)i * DM + c0;
    gcore<64, 128, 64, 128, true, false, 1>(ah + ao, al + ao, nullptr, (size_t)SEQ * SEQ,
                                            nullptr, nullptr, B, DM,
                                            nullptr, wsh + co, wsl + co, (size_t)SEQ * DM, nullptr,
                                            nullptr, nullptr, 0, 0, kceil);
}

// wsv: 64x64 tile, 256 thr, 2 CTAs/SM.
__global__ __launch_bounds__(256, 2) void gemm_wsv(const bf16* __restrict__ wsh,
                                                   const bf16* __restrict__ wsl,
                                                   const bf16* __restrict__ wvh,
                                                   const bf16* __restrict__ wvl,
                                                   bf16* __restrict__ oph,
                                                   bf16* __restrict__ opl) {
    int i0 = blockIdx.x * 64;
    int row = blockIdx.y;
    int b = row >> 4, h = row & 15, kv = h >> 2;
    size_t ao = ((size_t)row * SEQ + i0) * DM;
    size_t bo = (size_t)kv * HD;
    size_t co = ((size_t)b * SEQ + i0) * DM + h * HD;
    gcore<64, 64, 16, 256, true, true, 1>(wsh + ao, wsl + ao, nullptr, DM,
                                          wvh + bo, wvl + bo, nullptr, NKV * HD,
                                          nullptr, oph + co, opl + co, DM, nullptr,
                                          nullptr, nullptr, 0, 0, DM);
}

// ======================= Scores + softmax (causal-skipped) =================
template<int NQ4>
__device__ __forceinline__ void scores_body(const float qra[HD], const float qrb[HD],
                                            const float* __restrict__ kT,
                                            int ia, int ib, int lane,
                                            float* __restrict__ attn,
                                            bf16* __restrict__ ah_g,
                                            bf16* __restrict__ al_g,
                                            size_t basea, size_t baseb) {
    float sa[NQ4 * 4], sb[NQ4 * 4];
#pragma unroll
    for (int t = 0; t < NQ4 * 4; t++) { sa[t] = 0.f; sb[t] = 0.f; }

#pragma unroll 4
    for (int d = 0; d < HD; d++) {
        float qa = qra[d];
        float qb = qrb[d];
        const float* kd = kT + (size_t)d * SEQ + lane * 4;
#pragma unroll
        for (int q4 = 0; q4 < NQ4; q4++) {
            float4 kv4 = *(const float4*)&kd[q4 * 128];
            sa[q4 * 4 + 0] += qa * kv4.x;  sb[q4 * 4 + 0] += qb * kv4.x;
            sa[q4 * 4 + 1] += qa * kv4.y;  sb[q4 * 4 + 1] += qb * kv4.y;
            sa[q4 * 4 + 2] += qa * kv4.z;  sb[q4 * 4 + 2] += qb * kv4.z;
            sa[q4 * 4 + 3] += qa * kv4.w;  sb[q4 * 4 + 3] += qb * kv4.w;
        }
    }

    float ma = -INFINITY, mb = -INFINITY;
#pragma unroll
    for (int q4 = 0; q4 < NQ4; q4++)
#pragma unroll
        for (int e = 0; e < 4; e++) {
            int j = q4 * 128 + lane * 4 + e;
            int t = q4 * 4 + e;
            sa[t] = (j <= ia) ? sa[t] * 0.125f : -INFINITY;
            sb[t] = (j <= ib) ? sb[t] * 0.125f : -INFINITY;
            ma = fmaxf(ma, sa[t]);
            mb = fmaxf(mb, sb[t]);
        }
#pragma unroll
    for (int o = 16; o > 0; o >>= 1) {
        ma = fmaxf(ma, __shfl_xor_sync(0xFFFFFFFF, ma, o));
        mb = fmaxf(mb, __shfl_xor_sync(0xFFFFFFFF, mb, o));
    }
    float suma = 0.f, sumb = 0.f;
#pragma unroll
    for (int t = 0; t < NQ4 * 4; t++) {
        sa[t] = (sa[t] == -INFINITY) ? 0.f : __expf(sa[t] - ma);
        sb[t] = (sb[t] == -INFINITY) ? 0.f : __expf(sb[t] - mb);
        suma += sa[t];
        sumb += sb[t];
    }
#pragma unroll
    for (int o = 16; o > 0; o >>= 1) {
        suma += __shfl_xor_sync(0xFFFFFFFF, suma, o);
        sumb += __shfl_xor_sync(0xFFFFFFFF, sumb, o);
    }
    float inva = 1.0f / suma;
    float invb = 1.0f / sumb;

#pragma unroll
    for (int q4 = 0; q4 < NQ4; q4++) {
        int j = q4 * 128 + lane * 4;
        float4 va = make_float4(sa[q4 * 4] * inva, sa[q4 * 4 + 1] * inva,
                                sa[q4 * 4 + 2] * inva, sa[q4 * 4 + 3] * inva);
        float4 vb = make_float4(sb[q4 * 4] * invb, sb[q4 * 4 + 1] * invb,
                                sb[q4 * 4 + 2] * invb, sb[q4 * 4 + 3] * invb);
        *(float4*)&attn[basea + j] = va;
        *(float4*)&attn[baseb + j] = vb;
        split_write4(ah_g, al_g, basea + j, va);
        split_write4(ah_g, al_g, baseb + j, vb);
    }
    float4 z = make_float4(0.f, 0.f, 0.f, 0.f);
#pragma unroll
    for (int q4 = NQ4; q4 < 4; q4++) {
        int j = q4 * 128 + lane * 4;
        *(float4*)&attn[basea + j] = z;
        *(float4*)&attn[baseb + j] = z;
    }
}

__global__ __launch_bounds__(256) void scores2(const float* __restrict__ xq,
                                               const float* __restrict__ xkT,
                                               float* __restrict__ attn,
                                               bf16* __restrict__ ah_g,
                                               bf16* __restrict__ al_g) {
    int i0 = blockIdx.x * 16;
    int h = blockIdx.y, b = blockIdx.z;
    int kv = h >> 2;
    int tid = threadIdx.x;
    int w = tid >> 5, lane = tid & 31;

    __shared__ float qs[16][HD];
    {
        int idx = tid * 4;
        int row = idx >> 6, d = idx & 63;
        *(float4*)&qs[row][d] =
            *(const float4*)&xq[((size_t)(b * SEQ + i0 + row)) * DM + h * HD + d];
    }
    __syncthreads();

    int ia = i0 + w * 2;
    int ib = ia + 1;
    const float* kT = xkT + ((size_t)(b * NKV + kv)) * HD * SEQ;
    size_t basea = ((size_t)((b * NH + h) * SEQ + ia)) * SEQ;
    size_t baseb = basea + SEQ;
    int nq4 = min(4, (i0 + 16 + 127) >> 7);

    switch (nq4) {
        case 1: scores_body<1>(qs[w*2], qs[w*2+1], kT, ia, ib, lane, attn, ah_g, al_g, basea, baseb); break;
        case 2: scores_body<2>(qs[w*2], qs[w*2+1], kT, ia, ib, lane, attn, ah_g, al_g, basea, baseb); break;
        case 3: scores_body<3>(qs[w*2], qs[w*2+1], kT, ia, ib, lane, attn, ah_g, al_g, basea, baseb); break;
        default: scores_body<4>(qs[w*2], qs[w*2+1], kT, ia, ib, lane, attn, ah_g, al_g, basea, baseb); break;
    }
}

// ===========================================================================
extern "C" void kernel_launch(void* const* d_in, const int* in_sizes, int n_in,
                              void* d_out, int out_size) {
    const float* x       = (const float*)d_in[0];
    const float* symbols = (const float*)d_in[1];
    const float* fcos    = (const float*)d_in[2];
    const float* fsin    = (const float*)d_in[3];
    const float* wq      = (const float*)d_in[4];
    const float* wk      = (const float*)d_in[5];
    const float* wv      = (const float*)d_in[6];
    const float* wo      = (const float*)d_in[7];

    float* out  = (float*)d_out;
    float* attn = out + OUT_ELEMS;

    float *p_xq, *p_xkT;
    bf16 *p_xh, *p_xl, *p_wqkh, *p_wqkl, *p_wvh, *p_wvl, *p_woh, *p_wol;
    bf16 *p_ah, *p_al, *p_wsh, *p_wsl, *p_oph, *p_opl;
    cudaGetSymbolAddress((void**)&p_xq, g_xq);
    cudaGetSymbolAddress((void**)&p_xkT, g_xkT);
    cudaGetSymbolAddress((void**)&p_xh, g_xh);     cudaGetSymbolAddress((void**)&p_xl, g_xl);
    cudaGetSymbolAddress((void**)&p_wqkh, g_wqkh); cudaGetSymbolAddress((void**)&p_wqkl, g_wqkl);
    cudaGetSymbolAddress((void**)&p_wvh, g_wvh);   cudaGetSymbolAddress((void**)&p_wvl, g_wvl);
    cudaGetSymbolAddress((void**)&p_woh, g_woh);   cudaGetSymbolAddress((void**)&p_wol, g_wol);
    cudaGetSymbolAddress((void**)&p_ah, g_ah);     cudaGetSymbolAddress((void**)&p_al, g_al);
    cudaGetSymbolAddress((void**)&p_wsh, g_wsh);   cudaGetSymbolAddress((void**)&p_wsl, g_wsl);
    cudaGetSymbolAddress((void**)&p_oph, g_oph);   cudaGetSymbolAddress((void**)&p_opl, g_opl);

    cudaFuncSetAttribute(gemm_projqk, cudaFuncAttributeMaxDynamicSharedMemorySize, SM_T64);
    cudaFuncSetAttribute(gemm_wo,     cudaFuncAttributeMaxDynamicSharedMemorySize, SM_T64);
    cudaFuncSetAttribute(gemm_ws,     cudaFuncAttributeMaxDynamicSharedMemorySize, SM_T64);
    cudaFuncSetAttribute(gemm_wsv,    cudaFuncAttributeMaxDynamicSharedMemorySize, SM_WSV2);

    prep_all<<<4608, 256>>>(x, wq, wk, wv, wo, p_xh, p_xl, p_wqkh, p_wqkl,
                            p_wvh, p_wvl, p_woh, p_wol);                               // 0
    gemm_projqk<<<dim3(NQK / 128, NROWS / 64), 256, SM_T64>>>(p_xh, p_xl,
                                                              p_wqkh, p_wqkl,
                                                              p_xq, p_xkT,
                                                              fcos, fsin);             // 1
    scores2<<<dim3(SEQ / 16, NH, BSZ), 256>>>(p_xq, p_xkT, attn, p_ah, p_al);          // 2
    gemm_ws<<<dim3(DM / 128, SEQ), 128, SM_T64>>>(p_ah, p_al, symbols, p_wsh, p_wsl);  // 3  <- ncu
    gemm_wsv<<<dim3(SEQ / 64, 64), 256, SM_WSV2>>>(p_wsh, p_wsl, p_wvh, p_wvl,
                                                   p_oph, p_opl);                      // 4
    gemm_wo<<<dim3(DM / 128, NROWS / 64), 256, SM_T64>>>(p_oph, p_opl, p_woh, p_wol, out); // 5
}

// round 17
// speedup vs baseline: 1.1383x; 1.0661x over previous
#include <cuda_runtime.h>
#include <cuda_bf16.h>
#include <mma.h>
#include <math.h>
#include <cstdint>

using namespace nvcuda;

#define BSZ 4
#define SEQ 512
#define DM 1024
#define NH 16
#define NKV 4
#define HD 64
#define NROWS (BSZ*SEQ)          // 2048
#define OUT_ELEMS (BSZ*SEQ*DM)
#define NQK 1280                 // combined q|k output cols

typedef __nv_bfloat16 bf16;

// Scratch (device globals; no runtime allocation allowed)
__device__ float g_xq[NROWS * DM];                  // 8 MB (post-rope)
__device__ float g_xkT[BSZ * NKV * HD * SEQ];       // 2 MB (post-rope, transposed)
__device__ bf16 g_xh[NROWS * DM],  g_xl[NROWS * DM];
__device__ bf16 g_wqkh[DM * NQK], g_wqkl[DM * NQK];  // combined wq|wk
__device__ bf16 g_wvh[DM * NKV*HD], g_wvl[DM * NKV*HD];
__device__ bf16 g_woh[DM * DM],    g_wol[DM * DM];
__device__ bf16 g_ah[(size_t)64 * SEQ * SEQ], g_al[(size_t)64 * SEQ * SEQ];
__device__ bf16 g_wsh[(size_t)64 * SEQ * DM], g_wsl[(size_t)64 * SEQ * DM];
__device__ bf16 g_oph[NROWS * DM], g_opl[NROWS * DM];

// ===========================================================================
// helpers
// ===========================================================================
__device__ __forceinline__ void split_write4(bf16* __restrict__ H, bf16* __restrict__ L,
                                             size_t off, float4 v) {
    bf16 h0 = __float2bfloat16(v.x);
    bf16 h1 = __float2bfloat16(v.y);
    bf16 h2 = __float2bfloat16(v.z);
    bf16 h3 = __float2bfloat16(v.w);
    __nv_bfloat162 hh0; hh0.x = h0; hh0.y = h1;
    __nv_bfloat162 hh1; hh1.x = h2; hh1.y = h3;
    *(__nv_bfloat162*)(H + off)     = hh0;
    *(__nv_bfloat162*)(H + off + 2) = hh1;
    __nv_bfloat162 ll0, ll1;
    ll0.x = __float2bfloat16(v.x - __bfloat162float(h0));
    ll0.y = __float2bfloat16(v.y - __bfloat162float(h1));
    ll1.x = __float2bfloat16(v.z - __bfloat162float(h2));
    ll1.y = __float2bfloat16(v.w - __bfloat162float(h3));
    *(__nv_bfloat162*)(L + off)     = ll0;
    *(__nv_bfloat162*)(L + off + 2) = ll1;
}

__device__ __forceinline__ void cp_async16(uint32_t saddr, const void* gptr) {
    asm volatile("cp.async.cg.shared.global [%0], [%1], 16;" :: "r"(saddr), "l"(gptr));
}
__device__ __forceinline__ void cp_commit() { asm volatile("cp.async.commit_group;"); }
__device__ __forceinline__ void cp_wait0()  { asm volatile("cp.async.wait_group 0;"); }

// ======================= merged operand prep ===============================
__global__ void prep_all(const float* __restrict__ x, const float* __restrict__ wq,
                         const float* __restrict__ wk, const float* __restrict__ wv,
                         const float* __restrict__ wo,
                         bf16* xh, bf16* xl, bf16* wqkh, bf16* wqkl,
                         bf16* wvh, bf16* wvl, bf16* woh, bf16* wol) {
    int idx = blockIdx.x * blockDim.x + threadIdx.x;
    if (idx < 524288) {                       // x: 2048x1024
        float4 v = ((const float4*)x)[idx];
        split_write4(xh, xl, (size_t)idx * 4, v);
    } else if (idx < 786432) {                // wq -> wqk cols 0..1023
        int o = idx - 524288;
        int r = o >> 8, c4 = o & 255;
        float4 v = ((const float4*)wq)[o];
        split_write4(wqkh, wqkl, (size_t)r * NQK + c4 * 4, v);
    } else if (idx < 851968) {                // wk -> wqk cols 1024..1279
        int o = idx - 786432;
        int r = o >> 6, c4 = o & 63;
        float4 v = ((const float4*)wk)[o];
        split_write4(wqkh, wqkl, (size_t)r * NQK + 1024 + c4 * 4, v);
    } else if (idx < 917504) {                // wv
        int o = idx - 851968;
        float4 v = ((const float4*)wv)[o];
        split_write4(wvh, wvl, (size_t)o * 4, v);
    } else if (idx < 1179648) {               // wo
        int o = idx - 917504;
        float4 v = ((const float4*)wo)[o];
        split_write4(woh, wol, (size_t)o * 4, v);
    }
}

// ===========================================================================
// WMMA GEMM core. 3-term bf16 split (AhBh + AhBl + AlBh), fp32 acc.
// NT threads (NT/32 warps), warp tile 32 x WNW; CTA tile BM x BN; BK=32
// double-buffered cp.async.
// PA/PB: operand pre-split (h,l) bf16 -> cp.async straight to smem.
//        otherwise f32, register-staged with in-loop conversion.
// EPI: 0 = fp32 out; 1 = bf16 (h,l) out; 3 = RoPE + q/kT-split out (projqk).
// ===========================================================================
template<int BM, int BN, int WNW, int NT, bool PA, bool PB, int EPI>
__device__ __forceinline__ void gcore(
        const bf16* __restrict__ Ah_g, const bf16* __restrict__ Al_g,
        const float* __restrict__ Af_g, size_t lda,
        const bf16* __restrict__ Bh_g, const bf16* __restrict__ Bl_g,
        const float* __restrict__ Bf_g, size_t ldb,
        float* __restrict__ Cf, bf16* __restrict__ Ch, bf16* __restrict__ Cl,
        size_t ldc, float* __restrict__ Tp,
        const float* __restrict__ fcos, const float* __restrict__ fsin,
        int crow0, int ccol0, int kceil) {
    constexpr int APAD = 40;
    constexpr int BPAD = BN + 8;
    constexpr int ASZ  = BM * APAD;
    constexpr int BSZ_ = 32 * BPAD;
    constexpr int BUFSZ = 2 * ASZ + 2 * BSZ_;
    constexpr int NW  = NT / 32;
    constexpr int N8A = (BM * 4) / NT > 0 ? (BM * 4) / NT : 1;
    constexpr int N4A = (BM * 8) / NT;
    constexpr int N8B = (BN * 4) / NT;
    constexpr int N4B = (BN * 8) / NT;
    constexpr int WR = BM / 32;
    constexpr int NI = WNW / 16;
    static_assert(WR * (BN / WNW) == NW, "warp grid mismatch");

    extern __shared__ char smraw[];
    bf16* smbase = (bf16*)smraw;
    uint32_t smu = (uint32_t)__cvta_generic_to_shared(smbase);

    int tid = threadIdx.x;
    int w = tid >> 5;
    int wm = w % WR;
    int wn = w / WR;

    wmma::fragment<wmma::accumulator, 16, 16, 16, float> acc[2][NI];
#pragma unroll
    for (int mi = 0; mi < 2; mi++)
#pragma unroll
        for (int ni = 0; ni < NI; ni++) wmma::fill_fragment(acc[mi][ni], 0.0f);

    float4 raf[PA ? 1 : N4A];
    float4 rbf[PB ? 1 : N4B];

    auto issueA = [&](int k0, int bufsel) {
#pragma unroll
        for (int it = 0; it < N8A; it++) {
            int idx8 = tid + it * NT;
            int row = idx8 >> 2, kc = (idx8 & 3) * 8;
            uint32_t so = smu + (uint32_t)(bufsel * BUFSZ + row * APAD + kc) * 2;
            cp_async16(so, Ah_g + (size_t)row * lda + k0 + kc);
            cp_async16(so + ASZ * 2, Al_g + (size_t)row * lda + k0 + kc);
        }
    };
    auto issueB = [&](int k0, int bufsel) {
#pragma unroll
        for (int it = 0; it < N8B; it++) {
            int idx8 = tid + it * NT;
            int row = idx8 / (BN / 8), nc = (idx8 % (BN / 8)) * 8;
            uint32_t so = smu + (uint32_t)(bufsel * BUFSZ + 2 * ASZ + row * BPAD + nc) * 2;
            cp_async16(so, Bh_g + (size_t)(k0 + row) * ldb + nc);
            cp_async16(so + BSZ_ * 2, Bl_g + (size_t)(k0 + row) * ldb + nc);
        }
    };

    int nch = kceil >> 5;
    int cur = 0;

    if constexpr (PA) issueA(0, 0);
    if constexpr (PB) issueB(0, 0);
    if constexpr (PA || PB) cp_commit();
    if constexpr (!PA) {
#pragma unroll
        for (int it = 0; it < N4A; it++) {
            int idx4 = tid + it * NT;
            int row = idx4 >> 3, kc = (idx4 & 7) * 4;
            raf[it] = *(const float4*)&Af_g[(size_t)row * lda + kc];
        }
    }
    if constexpr (!PB) {
#pragma unroll
        for (int it = 0; it < N4B; it++) {
            int idx4 = tid + it * NT;
            int row = idx4 / (BN / 4), nc = (idx4 % (BN / 4)) * 4;
            rbf[it] = *(const float4*)&Bf_g[(size_t)row * ldb + nc];
        }
    }

    for (int ch = 0; ch < nch; ch++) {
        bf16* Ah = smbase + cur * BUFSZ;
        bf16* Al = Ah + ASZ;
        bf16* Bh = Al + ASZ;
        bf16* Bl = Bh + BSZ_;

        if constexpr (!PA) {
#pragma unroll
            for (int it = 0; it < N4A; it++) {
                int idx4 = tid + it * NT;
                int row = idx4 >> 3, kc = (idx4 & 7) * 4;
                split_write4(Ah, Al, row * APAD + kc, raf[it]);
            }
        }
        if constexpr (!PB) {
#pragma unroll
            for (int it = 0; it < N4B; it++) {
                int idx4 = tid + it * NT;
                int row = idx4 / (BN / 4), nc = (idx4 % (BN / 4)) * 4;
                split_write4(Bh, Bl, row * BPAD + nc, rbf[it]);
            }
        }
        if constexpr (PA || PB) cp_wait0();
        __syncthreads();

        if (ch + 1 < nch) {
            int k0 = (ch + 1) * 32;
            if constexpr (PA) issueA(k0, cur ^ 1);
            if constexpr (PB) issueB(k0, cur ^ 1);
            if constexpr (PA || PB) cp_commit();
            if constexpr (!PA) {
#pragma unroll
                for (int it = 0; it < N4A; it++) {
                    int idx4 = tid + it * NT;
                    int row = idx4 >> 3, kc = (idx4 & 7) * 4;
                    raf[it] = *(const float4*)&Af_g[(size_t)row * lda + k0 + kc];
                }
            }
            if constexpr (!PB) {
#pragma unroll
                for (int it = 0; it < N4B; it++) {
                    int idx4 = tid + it * NT;
                    int row = idx4 / (BN / 4), nc = (idx4 % (BN / 4)) * 4;
                    rbf[it] = *(const float4*)&Bf_g[(size_t)(k0 + row) * ldb + nc];
                }
            }
        }

#pragma unroll
        for (int kk = 0; kk < 32; kk += 16) {
            wmma::fragment<wmma::matrix_a, 16, 16, 16, bf16, wmma::row_major> ah[2], al[2];
#pragma unroll
            for (int mi = 0; mi < 2; mi++) {
                int r0 = (wm * 32 + mi * 16) * APAD + kk;
                wmma::load_matrix_sync(ah[mi], Ah + r0, APAD);
                wmma::load_matrix_sync(al[mi], Al + r0, APAD);
            }
#pragma unroll
            for (int ni = 0; ni < NI; ni++) {
                wmma::fragment<wmma::matrix_b, 16, 16, 16, bf16, wmma::row_major> bh, bl;
                int c0 = kk * BPAD + wn * WNW + ni * 16;
                wmma::load_matrix_sync(bh, Bh + c0, BPAD);
                wmma::load_matrix_sync(bl, Bl + c0, BPAD);
#pragma unroll
                for (int mi = 0; mi < 2; mi++) {
                    wmma::mma_sync(acc[mi][ni], ah[mi], bh, acc[mi][ni]);
                    wmma::mma_sync(acc[mi][ni], ah[mi], bl, acc[mi][ni]);
                    wmma::mma_sync(acc[mi][ni], al[mi], bh, acc[mi][ni]);
                }
            }
        }
        cur ^= 1;
    }

    // ---- epilogue via fp32 smem staging
    __syncthreads();
    float* stg = (float*)smraw;
#pragma unroll
    for (int mi = 0; mi < 2; mi++)
#pragma unroll
        for (int ni = 0; ni < NI; ni++)
            wmma::store_matrix_sync(stg + (size_t)(wm * 32 + mi * 16) * BN + wn * WNW + ni * 16,
                                    acc[mi][ni], BN, wmma::mem_row_major);
    __syncthreads();
    constexpr int NE4 = BM * BN / (4 * NT);
#pragma unroll
    for (int it = 0; it < NE4; it++) {
        int idx4 = tid + it * NT;
        int row = idx4 / (BN / 4), c = (idx4 % (BN / 4)) * 4;
        float4 v = *(const float4*)&stg[row * BN + c];
        if constexpr (EPI == 3) {
            int grow = crow0 + row;
            int gcol = ccol0 + c;
            int pos = grow & (SEQ - 1);
            int p = (gcol & 63) >> 1;
            float c0v = fcos[pos * 32 + p],     s0v = fsin[pos * 32 + p];
            float c1v = fcos[pos * 32 + p + 1], s1v = fsin[pos * 32 + p + 1];
            float4 o;
            o.x = v.x * c0v - v.y * s0v;
            o.y = v.x * s0v + v.y * c0v;
            o.z = v.z * c1v - v.w * s1v;
            o.w = v.z * s1v + v.w * c1v;
            if (gcol < DM) {
                *(float4*)&Cf[(size_t)grow * DM + gcol] = o;   // xq
            } else {
                int kvd = gcol - DM;                            // kv*64 + d
                int b = grow >> 9, j = grow & 511;
                float* base = Tp + ((size_t)(b * NKV * HD + kvd)) * SEQ + j;
                base[0]       = o.x;
                base[SEQ]     = o.y;
                base[2 * SEQ] = o.z;
                base[3 * SEQ] = o.w;
            }
        } else if constexpr (EPI == 1) {
            split_write4(Ch, Cl, (size_t)row * ldc + c, v);
        } else {
            *(float4*)&Cf[(size_t)row * ldc + c] = v;
        }
    }
}

// smem byte sizes (2 pipeline stages)
#define SM_T64  ((2*(64*40) + 2*(32*136)) * 2 * 2)   // 55296
#define SM_WSV2 ((2*(64*40) + 2*(32*72))  * 2 * 2)   // 38912

// ======================= GEMM wrappers =====================================
// Combined Q|K projection, fused RoPE + K-transpose epilogue. 64x128 tiles,
// 128 thr / 4 warps (warp tile 32x64), 3 CTAs/SM. grid (10, 32).
__global__ __launch_bounds__(128, 3) void gemm_projqk(const bf16* __restrict__ Ah,
                                                      const bf16* __restrict__ Al,
                                                      const bf16* __restrict__ Bh,
                                                      const bf16* __restrict__ Bl,
                                                      float* __restrict__ xq,
                                                      float* __restrict__ xkT,
                                                      const float* __restrict__ fcos,
                                                      const float* __restrict__ fsin) {
    size_t ao = (size_t)blockIdx.y * 64 * DM;
    size_t bo = (size_t)blockIdx.x * 128;
    gcore<64, 128, 64, 128, true, true, 3>(Ah + ao, Al + ao, nullptr, DM,
                                           Bh + bo, Bl + bo, nullptr, NQK,
                                           xq, nullptr, nullptr, DM, xkT,
                                           fcos, fsin, blockIdx.y * 64, blockIdx.x * 128, DM);
}

// Output projection: 64x128 tiles, 128 thr / 4 warps, 3 CTAs/SM. grid (8, 32).
__global__ __launch_bounds__(128, 3) void gemm_wo(const bf16* __restrict__ Ah,
                                                  const bf16* __restrict__ Al,
                                                  const bf16* __restrict__ Bh,
                                                  const bf16* __restrict__ Bl,
                                                  float* __restrict__ C) {
    size_t ao = (size_t)blockIdx.y * 64 * DM;
    size_t bo = (size_t)blockIdx.x * 128;
    float* Cb = C + (size_t)blockIdx.y * 64 * DM + (size_t)blockIdx.x * 128;
    gcore<64, 128, 64, 128, true, true, 0>(Ah + ao, Al + ao, nullptr, DM,
                                           Bh + bo, Bl + bo, nullptr, DM,
                                           Cb, nullptr, nullptr, DM, nullptr,
                                           nullptr, nullptr, 0, 0, DM);
}

// ws: 64x128 tile, 128 threads / 4 warps, warp tile 32x64, 3 CTAs/SM.
// Heavy (large i) blocks scheduled first.
__global__ __launch_bounds__(128, 3) void gemm_ws(const bf16* __restrict__ ah,
                                                  const bf16* __restrict__ al,
                                                  const float* __restrict__ symbols,
                                                  bf16* __restrict__ wsh,
                                                  bf16* __restrict__ wsl) {
    int i = SEQ - 1 - blockIdx.y;            // heavy K first
    int c0 = blockIdx.x * 128;
    int kceil = (i + 32) & ~31;              // attn[j>i]==0 exactly
    size_t ao = (size_t)i * SEQ;
    const float* B = symbols + (size_t)i * SEQ * DM + c0;
    size_t co = (size_t)i * DM + c0;
    gcore<64, 128, 64, 128, true, false, 1>(ah + ao, al + ao, nullptr, (size_t)SEQ * SEQ,
                                            nullptr, nullptr, B, DM,
                                            nullptr, wsh + co, wsl + co, (size_t)SEQ * DM, nullptr,
                                            nullptr, nullptr, 0, 0, kceil);
}

// wsv: 64x64 tile, 128 thr / 4 warps (warp tile 32x32), 4 CTAs/SM.
__global__ __launch_bounds__(128, 4) void gemm_wsv(const bf16* __restrict__ wsh,
                                                   const bf16* __restrict__ wsl,
                                                   const bf16* __restrict__ wvh,
                                                   const bf16* __restrict__ wvl,
                                                   bf16* __restrict__ oph,
                                                   bf16* __restrict__ opl) {
    int i0 = blockIdx.x * 64;
    int row = blockIdx.y;
    int b = row >> 4, h = row & 15, kv = h >> 2;
    size_t ao = ((size_t)row * SEQ + i0) * DM;
    size_t bo = (size_t)kv * HD;
    size_t co = ((size_t)b * SEQ + i0) * DM + h * HD;
    gcore<64, 64, 32, 128, true, true, 1>(wsh + ao, wsl + ao, nullptr, DM,
                                          wvh + bo, wvl + bo, nullptr, NKV * HD,
                                          nullptr, oph + co, opl + co, DM, nullptr,
                                          nullptr, nullptr, 0, 0, DM);
}

// ======================= Scores + softmax (causal-skipped) =================
template<int NQ4>
__device__ __forceinline__ void scores_body(const float qra[HD], const float qrb[HD],
                                            const float* __restrict__ kT,
                                            int ia, int ib, int lane,
                                            float* __restrict__ attn,
                                            bf16* __restrict__ ah_g,
                                            bf16* __restrict__ al_g,
                                            size_t basea, size_t baseb) {
    float sa[NQ4 * 4], sb[NQ4 * 4];
#pragma unroll
    for (int t = 0; t < NQ4 * 4; t++) { sa[t] = 0.f; sb[t] = 0.f; }

#pragma unroll 4
    for (int d = 0; d < HD; d++) {
        float qa = qra[d];
        float qb = qrb[d];
        const float* kd = kT + (size_t)d * SEQ + lane * 4;
#pragma unroll
        for (int q4 = 0; q4 < NQ4; q4++) {
            float4 kv4 = *(const float4*)&kd[q4 * 128];
            sa[q4 * 4 + 0] += qa * kv4.x;  sb[q4 * 4 + 0] += qb * kv4.x;
            sa[q4 * 4 + 1] += qa * kv4.y;  sb[q4 * 4 + 1] += qb * kv4.y;
            sa[q4 * 4 + 2] += qa * kv4.z;  sb[q4 * 4 + 2] += qb * kv4.z;
            sa[q4 * 4 + 3] += qa * kv4.w;  sb[q4 * 4 + 3] += qb * kv4.w;
        }
    }

    float ma = -INFINITY, mb = -INFINITY;
#pragma unroll
    for (int q4 = 0; q4 < NQ4; q4++)
#pragma unroll
        for (int e = 0; e < 4; e++) {
            int j = q4 * 128 + lane * 4 + e;
            int t = q4 * 4 + e;
            sa[t] = (j <= ia) ? sa[t] * 0.125f : -INFINITY;
            sb[t] = (j <= ib) ? sb[t] * 0.125f : -INFINITY;
            ma = fmaxf(ma, sa[t]);
            mb = fmaxf(mb, sb[t]);
        }
#pragma unroll
    for (int o = 16; o > 0; o >>= 1) {
        ma = fmaxf(ma, __shfl_xor_sync(0xFFFFFFFF, ma, o));
        mb = fmaxf(mb, __shfl_xor_sync(0xFFFFFFFF, mb, o));
    }
    float suma = 0.f, sumb = 0.f;
#pragma unroll
    for (int t = 0; t < NQ4 * 4; t++) {
        sa[t] = (sa[t] == -INFINITY) ? 0.f : __expf(sa[t] - ma);
        sb[t] = (sb[t] == -INFINITY) ? 0.f : __expf(sb[t] - mb);
        suma += sa[t];
        sumb += sb[t];
    }
#pragma unroll
    for (int o = 16; o > 0; o >>= 1) {
        suma += __shfl_xor_sync(0xFFFFFFFF, suma, o);
        sumb += __shfl_xor_sync(0xFFFFFFFF, sumb, o);
    }
    float inva = 1.0f / suma;
    float invb = 1.0f / sumb;

#pragma unroll
    for (int q4 = 0; q4 < NQ4; q4++) {
        int j = q4 * 128 + lane * 4;
        float4 va = make_float4(sa[q4 * 4] * inva, sa[q4 * 4 + 1] * inva,
                                sa[q4 * 4 + 2] * inva, sa[q4 * 4 + 3] * inva);
        float4 vb = make_float4(sb[q4 * 4] * invb, sb[q4 * 4 + 1] * invb,
                                sb[q4 * 4 + 2] * invb, sb[q4 * 4 + 3] * invb);
        *(float4*)&attn[basea + j] = va;
        *(float4*)&attn[baseb + j] = vb;
        split_write4(ah_g, al_g, basea + j, va);
        split_write4(ah_g, al_g, baseb + j, vb);
    }
    float4 z = make_float4(0.f, 0.f, 0.f, 0.f);
#pragma unroll
    for (int q4 = NQ4; q4 < 4; q4++) {
        int j = q4 * 128 + lane * 4;
        *(float4*)&attn[basea + j] = z;
        *(float4*)&attn[baseb + j] = z;
    }
}

__global__ __launch_bounds__(256) void scores2(const float* __restrict__ xq,
                                               const float* __restrict__ xkT,
                                               float* __restrict__ attn,
                                               bf16* __restrict__ ah_g,
                                               bf16* __restrict__ al_g) {
    int i0 = blockIdx.x * 16;
    int h = blockIdx.y, b = blockIdx.z;
    int kv = h >> 2;
    int tid = threadIdx.x;
    int w = tid >> 5, lane = tid & 31;

    __shared__ float qs[16][HD];
    {
        int idx = tid * 4;
        int row = idx >> 6, d = idx & 63;
        *(float4*)&qs[row][d] =
            *(const float4*)&xq[((size_t)(b * SEQ + i0 + row)) * DM + h * HD + d];
    }
    __syncthreads();

    int ia = i0 + w * 2;
    int ib = ia + 1;
    const float* kT = xkT + ((size_t)(b * NKV + kv)) * HD * SEQ;
    size_t basea = ((size_t)((b * NH + h) * SEQ + ia)) * SEQ;
    size_t baseb = basea + SEQ;
    int nq4 = min(4, (i0 + 16 + 127) >> 7);

    switch (nq4) {
        case 1: scores_body<1>(qs[w*2], qs[w*2+1], kT, ia, ib, lane, attn, ah_g, al_g, basea, baseb); break;
        case 2: scores_body<2>(qs[w*2], qs[w*2+1], kT, ia, ib, lane, attn, ah_g, al_g, basea, baseb); break;
        case 3: scores_body<3>(qs[w*2], qs[w*2+1], kT, ia, ib, lane, attn, ah_g, al_g, basea, baseb); break;
        default: scores_body<4>(qs[w*2], qs[w*2+1], kT, ia, ib, lane, attn, ah_g, al_g, basea, baseb); break;
    }
}

// ===========================================================================
extern "C" void kernel_launch(void* const* d_in, const int* in_sizes, int n_in,
                              void* d_out, int out_size) {
    const float* x       = (const float*)d_in[0];
    const float* symbols = (const float*)d_in[1];
    const float* fcos    = (const float*)d_in[2];
    const float* fsin    = (const float*)d_in[3];
    const float* wq      = (const float*)d_in[4];
    const float* wk      = (const float*)d_in[5];
    const float* wv      = (const float*)d_in[6];
    const float* wo      = (const float*)d_in[7];

    float* out  = (float*)d_out;
    float* attn = out + OUT_ELEMS;

    float *p_xq, *p_xkT;
    bf16 *p_xh, *p_xl, *p_wqkh, *p_wqkl, *p_wvh, *p_wvl, *p_woh, *p_wol;
    bf16 *p_ah, *p_al, *p_wsh, *p_wsl, *p_oph, *p_opl;
    cudaGetSymbolAddress((void**)&p_xq, g_xq);
    cudaGetSymbolAddress((void**)&p_xkT, g_xkT);
    cudaGetSymbolAddress((void**)&p_xh, g_xh);     cudaGetSymbolAddress((void**)&p_xl, g_xl);
    cudaGetSymbolAddress((void**)&p_wqkh, g_wqkh); cudaGetSymbolAddress((void**)&p_wqkl, g_wqkl);
    cudaGetSymbolAddress((void**)&p_wvh, g_wvh);   cudaGetSymbolAddress((void**)&p_wvl, g_wvl);
    cudaGetSymbolAddress((void**)&p_woh, g_woh);   cudaGetSymbolAddress((void**)&p_wol, g_wol);
    cudaGetSymbolAddress((void**)&p_ah, g_ah);     cudaGetSymbolAddress((void**)&p_al, g_al);
    cudaGetSymbolAddress((void**)&p_wsh, g_wsh);   cudaGetSymbolAddress((void**)&p_wsl, g_wsl);
    cudaGetSymbolAddress((void**)&p_oph, g_oph);   cudaGetSymbolAddress((void**)&p_opl, g_opl);

    cudaFuncSetAttribute(gemm_projqk, cudaFuncAttributeMaxDynamicSharedMemorySize, SM_T64);
    cudaFuncSetAttribute(gemm_wo,     cudaFuncAttributeMaxDynamicSharedMemorySize, SM_T64);
    cudaFuncSetAttribute(gemm_ws,     cudaFuncAttributeMaxDynamicSharedMemorySize, SM_T64);
    cudaFuncSetAttribute(gemm_wsv,    cudaFuncAttributeMaxDynamicSharedMemorySize, SM_WSV2);

    prep_all<<<4608, 256>>>(x, wq, wk, wv, wo, p_xh, p_xl, p_wqkh, p_wqkl,
                            p_wvh, p_wvl, p_woh, p_wol);                               // 0
    gemm_projqk<<<dim3(NQK / 128, NROWS / 64), 128, SM_T64>>>(p_xh, p_xl,
                                                              p_wqkh, p_wqkl,
                                                              p_xq, p_xkT,
                                                              fcos, fsin);             // 1
    scores2<<<dim3(SEQ / 16, NH, BSZ), 256>>>(p_xq, p_xkT, attn, p_ah, p_al);          // 2
    gemm_ws<<<dim3(DM / 128, SEQ), 128, SM_T64>>>(p_ah, p_al, symbols, p_wsh, p_wsl);  // 3  <- ncu
    gemm_wsv<<<dim3(SEQ / 64, 64), 128, SM_WSV2>>>(p_wsh, p_wsl, p_wvh, p_wvl,
                                                   p_oph, p_opl);                      // 4
    gemm_wo<<<dim3(DM / 128, NROWS / 64), 128, SM_T64>>>(p_oph, p_opl, p_woh, p_wol, out); // 5
}